// round 9
// baseline (speedup 1.0000x reference)
#include <cuda_runtime.h>
#include <cuda_bf16.h>
#include <math.h>

// ---------------- scratch (device globals; no allocation) ----------------
__device__ float g_gi[786432];      // 2048 x 384 (stage 3 only)
__device__ float g_short[8388608];  // 65536 x 128
__device__ float g_WB1[24576];      // Whh1 bf16 [384][128] (as float storage)
__device__ float g_WiB[3072];       // Wih1 bf16 [384][16]
__device__ float g_WB4[24576];      // gaWhh bf16 [384][128]
__device__ float g_WiB4[24576];     // gaWih bf16 [384][128]
__device__ float g_intra[262144];
__device__ float g_lg[262144];
__device__ float g_la[262144];
__device__ float g_Wh[262144];
__device__ float g_s12[4096];
__device__ float g_sec[2048];
__device__ float g_Wh2[2048];
__device__ float g_s12b[32];
__device__ float g_secout[2048];

// ---------------- helpers ----------------
__device__ __forceinline__ float sigmoidf_(float x) {
    return __fdividef(1.f, 1.f + __expf(-x));
}
__device__ __forceinline__ float tanhapx_(float x) {
    float y; asm("tanh.approx.f32 %0, %1;" : "=f"(y) : "f"(x)); return y;
}
__device__ __forceinline__ float sigapx_(float x) {
    return fmaf(tanhapx_(0.5f * x), 0.5f, 0.5f);
}
__device__ __forceinline__ void mma_bf16(float d[4], unsigned a0, unsigned a1,
                                         unsigned a2, unsigned a3,
                                         unsigned b0, unsigned b1) {
    asm volatile(
        "mma.sync.aligned.m16n8k16.row.col.f32.bf16.bf16.f32 "
        "{%0,%1,%2,%3},{%4,%5,%6,%7},{%8,%9},{%0,%1,%2,%3};\n"
        : "+f"(d[0]), "+f"(d[1]), "+f"(d[2]), "+f"(d[3])
        : "r"(a0), "r"(a1), "r"(a2), "r"(a3), "r"(b0), "r"(b1));
}
__device__ __forceinline__ float blockReduceSum128(float v, float* red) {
    #pragma unroll
    for (int o = 16; o; o >>= 1) v += __shfl_xor_sync(0xffffffffu, v, o);
    int w = threadIdx.x >> 5;
    if ((threadIdx.x & 31) == 0) red[w] = v;
    __syncthreads();
    float s = red[0] + red[1] + red[2] + red[3];
    __syncthreads();
    return s;
}

// ---------------- fp32 -> bf16 convert ----------------
__global__ void conv_bf16(const float* __restrict__ W, __nv_bfloat16* __restrict__ O, int n) {
    int i = blockIdx.x * 256 + threadIdx.x;
    if (i < n) O[i] = __float2bfloat16(W[i]);
}

// ---------------- stage-1: bf16 tensor-core GRU, fused pooling, persistent ----------------
template<int T>
__global__ void __launch_bounds__(512, 1) gru_mma(
    const float* __restrict__ xin,          // x rows of 80
    const __nv_bfloat16* __restrict__ WiB,  // Wih bf16 [384][16]
    const __nv_bfloat16* __restrict__ WB,   // Whh bf16 [384][128]
    const float* __restrict__ bih,
    const float* __restrict__ bhh,
    const float* __restrict__ aw, const float* __restrict__ ab,
    float* __restrict__ outp,               // [seq][128] pooled
    int nBatch)
{
    extern __shared__ char smc[];
    __nv_bfloat16* hsm = (__nv_bfloat16*)smc;           // [T][16][136]
    __nv_bfloat16* x_b = hsm + T * 16 * 136;            // [16][88]
    float* sc_s = (float*)(x_b + 16 * 88);              // [16][T]

    int tid = threadIdx.x;
    int w = tid >> 5, lane = tid & 31;
    int g = lane >> 2, tig = lane & 3;
    int c0 = w * 8 + 2 * tig;

    unsigned wb[8][3][2];
    #pragma unroll
    for (int kt = 0; kt < 8; kt++) {
        #pragma unroll
        for (int nt = 0; nt < 3; nt++) {
            const __nv_bfloat16* p = WB + (size_t)(nt * 128 + w * 8 + g) * 128 + kt * 16;
            wb[kt][nt][0] = *(const unsigned*)(p + 2 * tig);
            wb[kt][nt][1] = *(const unsigned*)(p + 8 + 2 * tig);
        }
    }
    unsigned wbi[3][2];
    #pragma unroll
    for (int nt = 0; nt < 3; nt++) {
        const __nv_bfloat16* p = WiB + (size_t)(nt * 128 + w * 8 + g) * 16;
        wbi[nt][0] = *(const unsigned*)(p + 2 * tig);
        wbi[nt][1] = *(const unsigned*)(p + 8 + 2 * tig);
    }
    float2 bhr2 = *(const float2*)(bhh + c0);
    float2 bhz2 = *(const float2*)(bhh + 128 + c0);
    float2 bhn2 = *(const float2*)(bhh + 256 + c0);
    float2 bir2 = *(const float2*)(bih + c0);
    float2 biz2 = *(const float2*)(bih + 128 + c0);
    float2 bin2 = *(const float2*)(bih + 256 + c0);
    float ab0 = __ldg(ab);
    float awv[4];
    #pragma unroll
    for (int q = 0; q < 4; q++) awv[q] = __ldg(aw + lane + 32 * q);

    for (int b = blockIdx.x; b < nBatch; b += gridDim.x) {
        size_t seq0 = (size_t)b * 16;

        for (int i = tid; i < 16 * 80; i += 512)
            x_b[(i / 80) * 88 + (i % 80)] = __float2bfloat16(__ldg(xin + seq0 * 80 + i));
        __syncthreads();

        for (int t = 0; t < T; t++) {
            float ra[4] = {0, 0, 0, 0}, rb[4] = {0, 0, 0, 0};
            float za[4] = {0, 0, 0, 0}, zb[4] = {0, 0, 0, 0};
            float na[4] = {0, 0, 0, 0}, nb[4] = {0, 0, 0, 0};
            float gn_[4] = {0, 0, 0, 0};
            {
                int kc = t * 16 + 2 * tig;
                unsigned a0 = *(const unsigned*)(x_b + g * 88 + kc);
                unsigned a1 = *(const unsigned*)(x_b + (g + 8) * 88 + kc);
                unsigned a2 = *(const unsigned*)(x_b + g * 88 + kc + 8);
                unsigned a3 = *(const unsigned*)(x_b + (g + 8) * 88 + kc + 8);
                mma_bf16(ra, a0, a1, a2, a3, wbi[0][0], wbi[0][1]);
                mma_bf16(za, a0, a1, a2, a3, wbi[1][0], wbi[1][1]);
                mma_bf16(gn_, a0, a1, a2, a3, wbi[2][0], wbi[2][1]);
            }
            if (t > 0) {
                const __nv_bfloat16* hb = hsm + (size_t)(t - 1) * 16 * 136;
                #pragma unroll
                for (int kt = 0; kt < 8; kt++) {
                    int kc = kt * 16 + 2 * tig;
                    unsigned a0 = *(const unsigned*)(hb + g * 136 + kc);
                    unsigned a1 = *(const unsigned*)(hb + (g + 8) * 136 + kc);
                    unsigned a2 = *(const unsigned*)(hb + g * 136 + kc + 8);
                    unsigned a3 = *(const unsigned*)(hb + (g + 8) * 136 + kc + 8);
                    if (kt & 1) {
                        mma_bf16(rb, a0, a1, a2, a3, wb[kt][0][0], wb[kt][0][1]);
                        mma_bf16(zb, a0, a1, a2, a3, wb[kt][1][0], wb[kt][1][1]);
                        mma_bf16(nb, a0, a1, a2, a3, wb[kt][2][0], wb[kt][2][1]);
                    } else {
                        mma_bf16(ra, a0, a1, a2, a3, wb[kt][0][0], wb[kt][0][1]);
                        mma_bf16(za, a0, a1, a2, a3, wb[kt][1][0], wb[kt][1][1]);
                        mma_bf16(na, a0, a1, a2, a3, wb[kt][2][0], wb[kt][2][1]);
                    }
                }
            }
            {
                __nv_bfloat16* hcur = hsm + (size_t)t * 16 * 136;
                const __nv_bfloat16* hprv = hsm + (size_t)(t > 0 ? t - 1 : 0) * 16 * 136;
                #pragma unroll
                for (int hh = 0; hh < 2; hh++) {
                    int row = hh ? g + 8 : g;
                    int e = hh * 2;
                    float gr0 = ra[e] + rb[e] + bhr2.x + bir2.x;
                    float gr1 = ra[e + 1] + rb[e + 1] + bhr2.y + bir2.y;
                    float gz0 = za[e] + zb[e] + bhz2.x + biz2.x;
                    float gz1 = za[e + 1] + zb[e + 1] + bhz2.y + biz2.y;
                    float gn0 = na[e] + nb[e] + bhn2.x;
                    float gn1 = na[e + 1] + nb[e + 1] + bhn2.y;
                    float in0 = gn_[e] + bin2.x, in1 = gn_[e + 1] + bin2.y;
                    float r0 = sigapx_(gr0), r1 = sigapx_(gr1);
                    float z0 = sigapx_(gz0), z1 = sigapx_(gz1);
                    float n0 = tanhapx_(fmaf(r0, gn0, in0));
                    float n1 = tanhapx_(fmaf(r1, gn1, in1));
                    float h0, h1;
                    if (t == 0) {
                        h0 = (1.f - z0) * n0;
                        h1 = (1.f - z1) * n1;
                    } else {
                        float2 hp2 = __bfloat1622float2(
                            *(const __nv_bfloat162*)(hprv + row * 136 + c0));
                        h0 = fmaf(z0, hp2.x - n0, n0);
                        h1 = fmaf(z1, hp2.y - n1, n1);
                    }
                    *(__nv_bfloat162*)(hcur + row * 136 + c0) =
                        __float22bfloat162_rn(make_float2(h0, h1));
                }
            }
            __syncthreads();
        }

        {
            int s = w;
            for (int t = 0; t < T; t++) {
                float v = 0.f;
                #pragma unroll
                for (int q = 0; q < 4; q++)
                    v = fmaf(__bfloat162float(hsm[t * 16 * 136 + s * 136 + lane + 32 * q]),
                             awv[q], v);
                #pragma unroll
                for (int o = 16; o; o >>= 1) v += __shfl_xor_sync(0xffffffffu, v, o);
                if (lane == 0) sc_s[s * T + t] = v + ab0;
            }
        }
        __syncthreads();
        {
            int j = tid & 127, sb = tid >> 7;
            #pragma unroll
            for (int i = 0; i < 4; i++) {
                int s = sb + i * 4;
                float m = -1e30f;
                for (int t = 0; t < T; t++) m = fmaxf(m, sc_s[s * T + t]);
                float Z = 0.f, acc = 0.f;
                for (int t = 0; t < T; t++) {
                    float wt = __expf(sc_s[s * T + t] - m);
                    Z += wt;
                    acc = fmaf(wt, __bfloat162float(hsm[t * 16 * 136 + s * 136 + j]), acc);
                }
                outp[(seq0 + s) * 128 + j] = acc / Z;
            }
        }
    }
}

// ---------------- stage-4 fused: gi-MMA + GRU + online-softmax pooling ----------------
// 16 stocks/CTA, 128 CTAs. Wih in smem (bf16 [384][136]), Whh frags in regs.
// x_t tile double-buffered; pooling online (no h history).
__global__ void __launch_bounds__(512, 1) gru4_fused(
    const float* __restrict__ shortb,        // [65536][128]: row = stock*32 + week
    const __nv_bfloat16* __restrict__ WiB,   // gaWih bf16 [384][128]
    const __nv_bfloat16* __restrict__ WB,    // gaWhh bf16 [384][128]
    const float* __restrict__ bih, const float* __restrict__ bhh,
    const float* __restrict__ aw, const float* __restrict__ ab,
    float* __restrict__ outp)                // [2048][128]
{
    constexpr int T = 32;
    extern __shared__ char smc[];
    __nv_bfloat16* wih_s = (__nv_bfloat16*)smc;          // [384][136]
    __nv_bfloat16* x_s   = wih_s + 384 * 136;            // [2][16][136]
    __nv_bfloat16* h_s   = x_s + 2 * 16 * 136;           // [2][16][136]
    float* scp = (float*)(h_s + 2 * 16 * 136);           // [2][16][16]

    int tid = threadIdx.x;
    int w = tid >> 5, lane = tid & 31;
    int g = lane >> 2, tig = lane & 3;
    int c0 = w * 8 + 2 * tig;
    size_t seq0 = (size_t)blockIdx.x * 16;

    // stage Wih to smem
    for (int i = tid; i < 384 * 128; i += 512) {
        int col = i >> 7, k = i & 127;
        wih_s[col * 136 + k] = WiB[i];
    }
    // Whh frags to regs
    unsigned wb[8][3][2];
    #pragma unroll
    for (int kt = 0; kt < 8; kt++) {
        #pragma unroll
        for (int nt = 0; nt < 3; nt++) {
            const __nv_bfloat16* p = WB + (size_t)(nt * 128 + w * 8 + g) * 128 + kt * 16;
            wb[kt][nt][0] = *(const unsigned*)(p + 2 * tig);
            wb[kt][nt][1] = *(const unsigned*)(p + 8 + 2 * tig);
        }
    }
    // biases: r,z combined (bih+bhh); n kept split
    float2 t1, t2;
    t1 = *(const float2*)(bih + c0);       t2 = *(const float2*)(bhh + c0);
    float2 br2 = make_float2(t1.x + t2.x, t1.y + t2.y);
    t1 = *(const float2*)(bih + 128 + c0); t2 = *(const float2*)(bhh + 128 + c0);
    float2 bz2 = make_float2(t1.x + t2.x, t1.y + t2.y);
    float2 bin2 = *(const float2*)(bih + 256 + c0);
    float2 bhn2 = *(const float2*)(bhh + 256 + c0);
    float2 aw2 = *(const float2*)(aw + c0);
    float ab0 = __ldg(ab);

    // pooling state
    float accP[4] = {0.f, 0.f, 0.f, 0.f};
    float mrun[2] = {-1e30f, -1e30f};
    float zrun[2] = {0.f, 0.f};

    // stage x_0
    for (int i = tid; i < 2048; i += 512) {
        int s = i >> 7, j = i & 127;
        x_s[s * 136 + j] = __float2bfloat16(__ldg(shortb + ((seq0 + s) * 32 + 0) * 128 + j));
    }
    __syncthreads();

    for (int t = 0; t < T; t++) {
        int cur = t & 1, nxt = cur ^ 1;
        // prefetch x_{t+1} into registers
        float xf[4];
        if (t + 1 < T) {
            #pragma unroll
            for (int q = 0; q < 4; q++) {
                int i = tid + q * 512;
                int s = i >> 7, j = i & 127;
                xf[q] = __ldg(shortb + ((seq0 + s) * 32 + (t + 1)) * 128 + j);
            }
        }
        float ra[4] = {0, 0, 0, 0}, rb[4] = {0, 0, 0, 0};
        float za[4] = {0, 0, 0, 0}, zb[4] = {0, 0, 0, 0};
        float na[4] = {0, 0, 0, 0}, nb[4] = {0, 0, 0, 0};
        float aI[4] = {0, 0, 0, 0};

        // gi MMAs: A = x_s[cur], B streamed from wih_s
        {
            const __nv_bfloat16* xb = x_s + cur * (16 * 136);
            #pragma unroll
            for (int kt = 0; kt < 8; kt++) {
                int kc = kt * 16 + 2 * tig;
                unsigned a0 = *(const unsigned*)(xb + g * 136 + kc);
                unsigned a1 = *(const unsigned*)(xb + (g + 8) * 136 + kc);
                unsigned a2 = *(const unsigned*)(xb + g * 136 + kc + 8);
                unsigned a3 = *(const unsigned*)(xb + (g + 8) * 136 + kc + 8);
                const __nv_bfloat16* p0 = wih_s + (w * 8 + g) * 136 + kt * 16;
                unsigned b0 = *(const unsigned*)(p0 + 2 * tig);
                unsigned b1 = *(const unsigned*)(p0 + 8 + 2 * tig);
                mma_bf16(ra, a0, a1, a2, a3, b0, b1);
                const __nv_bfloat16* p1 = wih_s + (128 + w * 8 + g) * 136 + kt * 16;
                b0 = *(const unsigned*)(p1 + 2 * tig);
                b1 = *(const unsigned*)(p1 + 8 + 2 * tig);
                mma_bf16(za, a0, a1, a2, a3, b0, b1);
                const __nv_bfloat16* p2 = wih_s + (256 + w * 8 + g) * 136 + kt * 16;
                b0 = *(const unsigned*)(p2 + 2 * tig);
                b1 = *(const unsigned*)(p2 + 8 + 2 * tig);
                mma_bf16(aI, a0, a1, a2, a3, b0, b1);
            }
        }
        // h MMAs
        if (t > 0) {
            const __nv_bfloat16* hb = h_s + nxt * (16 * 136);  // (t-1)&1 == nxt
            #pragma unroll
            for (int kt = 0; kt < 8; kt++) {
                int kc = kt * 16 + 2 * tig;
                unsigned a0 = *(const unsigned*)(hb + g * 136 + kc);
                unsigned a1 = *(const unsigned*)(hb + (g + 8) * 136 + kc);
                unsigned a2 = *(const unsigned*)(hb + g * 136 + kc + 8);
                unsigned a3 = *(const unsigned*)(hb + (g + 8) * 136 + kc + 8);
                if (kt & 1) {
                    mma_bf16(rb, a0, a1, a2, a3, wb[kt][0][0], wb[kt][0][1]);
                    mma_bf16(zb, a0, a1, a2, a3, wb[kt][1][0], wb[kt][1][1]);
                    mma_bf16(nb, a0, a1, a2, a3, wb[kt][2][0], wb[kt][2][1]);
                } else {
                    mma_bf16(ra, a0, a1, a2, a3, wb[kt][0][0], wb[kt][0][1]);
                    mma_bf16(za, a0, a1, a2, a3, wb[kt][1][0], wb[kt][1][1]);
                    mma_bf16(na, a0, a1, a2, a3, wb[kt][2][0], wb[kt][2][1]);
                }
            }
        }
        // gates (in-register) + h store + score partials
        float hv[4];
        {
            __nv_bfloat16* hcur = h_s + cur * (16 * 136);
            const __nv_bfloat16* hprv = h_s + nxt * (16 * 136);
            #pragma unroll
            for (int hh = 0; hh < 2; hh++) {
                int row = hh ? g + 8 : g;
                int e = hh * 2;
                float gr0 = ra[e] + rb[e] + br2.x, gr1 = ra[e + 1] + rb[e + 1] + br2.y;
                float gz0 = za[e] + zb[e] + bz2.x, gz1 = za[e + 1] + zb[e + 1] + bz2.y;
                float gn0 = na[e] + nb[e] + bhn2.x, gn1 = na[e + 1] + nb[e + 1] + bhn2.y;
                float in0 = aI[e] + bin2.x, in1 = aI[e + 1] + bin2.y;
                float r0 = sigapx_(gr0), r1 = sigapx_(gr1);
                float z0 = sigapx_(gz0), z1 = sigapx_(gz1);
                float n0 = tanhapx_(fmaf(r0, gn0, in0));
                float n1 = tanhapx_(fmaf(r1, gn1, in1));
                float h0, h1;
                if (t == 0) {
                    h0 = (1.f - z0) * n0;
                    h1 = (1.f - z1) * n1;
                } else {
                    float2 hp2 = __bfloat1622float2(
                        *(const __nv_bfloat162*)(hprv + row * 136 + c0));
                    h0 = fmaf(z0, hp2.x - n0, n0);
                    h1 = fmaf(z1, hp2.y - n1, n1);
                }
                hv[e] = h0; hv[e + 1] = h1;
                *(__nv_bfloat162*)(hcur + row * 136 + c0) =
                    __float22bfloat162_rn(make_float2(h0, h1));
            }
        }
        // score partials: reduce over tig within warp, stash per (row, warp)
        {
            float p0 = fmaf(hv[0], aw2.x, hv[1] * aw2.y);
            float p1 = fmaf(hv[2], aw2.x, hv[3] * aw2.y);
            p0 += __shfl_xor_sync(0xffffffffu, p0, 1);
            p0 += __shfl_xor_sync(0xffffffffu, p0, 2);
            p1 += __shfl_xor_sync(0xffffffffu, p1, 1);
            p1 += __shfl_xor_sync(0xffffffffu, p1, 2);
            if (tig == 0) {
                scp[cur * 256 + g * 16 + w] = p0;
                scp[cur * 256 + (g + 8) * 16 + w] = p1;
            }
        }
        // store x_{t+1}
        if (t + 1 < T) {
            #pragma unroll
            for (int q = 0; q < 4; q++) {
                int i = tid + q * 512;
                int s = i >> 7, j = i & 127;
                x_s[nxt * (16 * 136) + s * 136 + j] = __float2bfloat16(xf[q]);
            }
        }
        __syncthreads();
        // online-softmax pooling update (scp double-buffered: no extra barrier)
        #pragma unroll
        for (int hh = 0; hh < 2; hh++) {
            int row = hh ? g + 8 : g;
            float sv = ab0;
            #pragma unroll
            for (int ww = 0; ww < 16; ww++) sv += scp[cur * 256 + row * 16 + ww];
            float mn = fmaxf(mrun[hh], sv);
            float so = __expf(mrun[hh] - mn);
            float sn = __expf(sv - mn);
            zrun[hh] = zrun[hh] * so + sn;
            accP[hh * 2 + 0] = accP[hh * 2 + 0] * so + sn * hv[hh * 2 + 0];
            accP[hh * 2 + 1] = accP[hh * 2 + 1] * so + sn * hv[hh * 2 + 1];
            mrun[hh] = mn;
        }
    }
    // write pooled output
    #pragma unroll
    for (int hh = 0; hh < 2; hh++) {
        int row = hh ? g + 8 : g;
        float inv = __fdividef(1.f, zrun[hh]);
        *(float2*)(outp + (seq0 + row) * 128 + c0) =
            make_float2(accP[hh * 2] * inv, accP[hh * 2 + 1] * inv);
    }
}

// ---------------- bf16 GEMM: C[M,384] = A[M,128] @ W[384,128]^T + bias (stage 3) ----------------
__global__ void __launch_bounds__(256) gemm_bf16(
    const float* __restrict__ A, const float* __restrict__ W,
    const float* __restrict__ bias, float* __restrict__ C)
{
    extern __shared__ char gsc[];
    __nv_bfloat16* As = (__nv_bfloat16*)gsc;  // 64 x 136
    __nv_bfloat16* Ws = As + 64 * 136;        // 64 x 136
    int tid = threadIdx.x;
    size_t m0 = (size_t)blockIdx.x * 64;
    int n0 = blockIdx.y * 64;
    for (int i = tid; i < 2048; i += 256) {
        int r = i >> 5, c4 = (i & 31) * 4;
        float4 av = *(const float4*)(A + (m0 + r) * 128 + c4);
        float4 wv = *(const float4*)(W + (size_t)(n0 + r) * 128 + c4);
        *(__nv_bfloat162*)(As + r * 136 + c4)     = __float22bfloat162_rn(make_float2(av.x, av.y));
        *(__nv_bfloat162*)(As + r * 136 + c4 + 2) = __float22bfloat162_rn(make_float2(av.z, av.w));
        *(__nv_bfloat162*)(Ws + r * 136 + c4)     = __float22bfloat162_rn(make_float2(wv.x, wv.y));
        *(__nv_bfloat162*)(Ws + r * 136 + c4 + 2) = __float22bfloat162_rn(make_float2(wv.z, wv.w));
    }
    __syncthreads();
    int w = tid >> 5, lane = tid & 31;
    int wm = w & 3, wn = w >> 2;
    int g = lane >> 2, tig = lane & 3;
    int mrow = wm * 16, nbase = wn * 32;
    float d[4][4] = {};
    #pragma unroll
    for (int k0 = 0; k0 < 128; k0 += 16) {
        int kc = k0 + 2 * tig;
        unsigned a0 = *(const unsigned*)(As + (mrow + g) * 136 + kc);
        unsigned a1 = *(const unsigned*)(As + (mrow + g + 8) * 136 + kc);
        unsigned a2 = *(const unsigned*)(As + (mrow + g) * 136 + kc + 8);
        unsigned a3 = *(const unsigned*)(As + (mrow + g + 8) * 136 + kc + 8);
        #pragma unroll
        for (int f = 0; f < 4; f++) {
            unsigned b0 = *(const unsigned*)(Ws + (nbase + f * 8 + g) * 136 + kc);
            unsigned b1 = *(const unsigned*)(Ws + (nbase + f * 8 + g) * 136 + kc + 8);
            mma_bf16(d[f], a0, a1, a2, a3, b0, b1);
        }
    }
    #pragma unroll
    for (int f = 0; f < 4; f++) {
        int col = n0 + nbase + f * 8 + 2 * tig;
        float2 b2 = *(const float2*)(bias + col);
        *(float2*)(C + (m0 + mrow + g) * 384 + col) =
            make_float2(d[f][0] + b2.x, d[f][1] + b2.y);
        *(float2*)(C + (m0 + mrow + g + 8) * 384 + col) =
            make_float2(d[f][2] + b2.x, d[f][3] + b2.y);
    }
}

// ---------------- single-step GRU with h0=0 (stage 3) ----------------
__global__ void gru_single(const float* __restrict__ gi, const float* __restrict__ bhh,
                           float* __restrict__ lg)
{
    int idx = blockIdx.x * 256 + threadIdx.x;
    int s = idx >> 7, j = idx & 127;
    const float* gp = gi + (size_t)s * 384;
    float r = sigmoidf_(__ldg(gp + j) + __ldg(bhh + j));
    float z = sigmoidf_(__ldg(gp + 128 + j) + __ldg(bhh + 128 + j));
    float n = tanhf(__ldg(gp + 256 + j) + r * __ldg(bhh + 256 + j));
    lg[idx] = (1.f - z) * n;
}

// ---------------- GAT prep ----------------
__global__ void __launch_bounds__(128) gat_prep(
    const float* __restrict__ Hin, int rstride,
    const float* __restrict__ W, const float* __restrict__ a,
    float* __restrict__ Wh, float* __restrict__ s12, int M)
{
    __shared__ float red[4];
    int m = blockIdx.x, n = threadIdx.x;
    const float* hr = Hin + (size_t)m * rstride;
    float acc = 0.f;
    #pragma unroll 8
    for (int k = 0; k < 128; k++) acc = fmaf(__ldg(hr + k), W[k * 128 + n], acc);
    Wh[(size_t)m * 128 + n] = acc;
    float s1 = blockReduceSum128(acc * __ldg(a + n), red);
    float s2 = blockReduceSum128(acc * __ldg(a + 128 + n), red);
    if (n == 0) { s12[m] = s1; s12[M + m] = s2; }
}

// ---------------- GAT intra attention ----------------
__global__ void __launch_bounds__(128) gat_intra_attn(
    const float* __restrict__ Wh, const float* __restrict__ s12,
    const int* __restrict__ sect, float* __restrict__ out)
{
    __shared__ float red[4];
    __shared__ int lst[2048];
    __shared__ float wgt[2048];
    __shared__ int cnt;
    int i = blockIdx.x, d = threadIdx.x;
    if (d == 0) cnt = 0;
    __syncthreads();
    int si = __ldg(sect + i);
    for (int j = d; j < 2048; j += 128)
        if (__ldg(sect + j) == si) { int p = atomicAdd(&cnt, 1); lst[p] = j; }
    __syncthreads();
    int n = cnt;
    float s1i = s12[i];
    float lm = -1e30f;
    for (int p = d; p < n; p += 128) {
        float e = s1i + s12[2048 + lst[p]];
        e = e >= 0.f ? e : 0.2f * e;
        lm = fmaxf(lm, e);
    }
    #pragma unroll
    for (int o = 16; o; o >>= 1) lm = fmaxf(lm, __shfl_xor_sync(0xffffffffu, lm, o));
    if ((d & 31) == 0) red[d >> 5] = lm;
    __syncthreads();
    float m = fmaxf(fmaxf(red[0], red[1]), fmaxf(red[2], red[3]));
    __syncthreads();
    float lz = 0.f;
    for (int p = d; p < n; p += 128) {
        float e = s1i + s12[2048 + lst[p]];
        e = e >= 0.f ? e : 0.2f * e;
        float w = __expf(e - m);
        wgt[p] = w;
        lz += w;
    }
    float Z = blockReduceSum128(lz, red);
    float inv = __fdividef(1.f, Z);
    float acc = 0.f;
    #pragma unroll 4
    for (int p = 0; p < n; p++) acc = fmaf(wgt[p], Wh[(size_t)lst[p] * 128 + d], acc);
    acc *= inv;
    out[(size_t)i * 128 + d] = acc > 0.f ? acc : expm1f(acc);
}

// ---------------- sector mean ----------------
__global__ void __launch_bounds__(128) sector_mean(
    const float* __restrict__ lg, const int* __restrict__ sect, float* __restrict__ sec)
{
    int ns = blockIdx.x, d = threadIdx.x;
    float s = 0.f;
    int c = 0;
    for (int i = 0; i < 2048; i++) {
        if (__ldg(sect + i) == ns) { s += lg[(size_t)i * 128 + d]; c++; }
    }
    sec[ns * 128 + d] = s / fmaxf((float)c, 1.f);
}

// ---------------- GAT inter attention ----------------
__global__ void __launch_bounds__(128) gat_inter_attn(
    const float* __restrict__ Wh, const float* __restrict__ s12,
    const int* __restrict__ adj, float* __restrict__ out)
{
    __shared__ float e[16];
    int i = blockIdx.x, d = threadIdx.x;
    if (d < 16) {
        float v = s12[i] + s12[16 + d];
        v = v >= 0.f ? v : 0.2f * v;
        e[d] = (__ldg(adj + i * 16 + d) > 0) ? v : -9.0e15f;
    }
    __syncthreads();
    float m = -1e30f;
    #pragma unroll
    for (int j = 0; j < 16; j++) m = fmaxf(m, e[j]);
    float Z = 0.f, acc = 0.f;
    #pragma unroll
    for (int j = 0; j < 16; j++) {
        float w = __expf(e[j] - m);
        Z += w;
        acc = fmaf(w, Wh[j * 128 + d], acc);
    }
    acc = __fdividef(acc, Z);
    out[i * 128 + d] = acc > 0.f ? acc : expm1f(acc);
}

// ---------------- fusion + heads ----------------
__global__ void __launch_bounds__(128) fusion_heads(
    const float* __restrict__ lg, const float* __restrict__ la,
    const float* __restrict__ secout, const int* __restrict__ sect,
    const float* __restrict__ fw, const float* __restrict__ fb,
    const float* __restrict__ rw, const float* __restrict__ rb,
    const float* __restrict__ mw, const float* __restrict__ mb,
    float* __restrict__ out)
{
    __shared__ float red[4];
    int i = blockIdx.x, n = threadIdx.x;
    int si = __ldg(sect + i);
    const float* lgr = lg + (size_t)i * 128;
    const float* lar = la + (size_t)i * 128;
    const float* ser = secout + (size_t)si * 128;
    float acc = __ldg(fb + n);
    #pragma unroll 4
    for (int k = 0; k < 128; k++) acc = fmaf(__ldg(lgr + k), fw[k * 128 + n], acc);
    #pragma unroll 4
    for (int k = 0; k < 128; k++) acc = fmaf(__ldg(lar + k), fw[(128 + k) * 128 + n], acc);
    #pragma unroll 4
    for (int k = 0; k < 128; k++) acc = fmaf(__ldg(ser + k), fw[(256 + k) * 128 + n], acc);
    float r  = blockReduceSum128(acc * __ldg(rw + n), red);
    float mv = blockReduceSum128(acc * __ldg(mw + n), red);
    if (n == 0) {
        out[i]        = r + __ldg(rb);
        out[2048 + i] = sigmoidf_(mv + __ldg(mb));
    }
}

// ---------------- launch ----------------
extern "C" void kernel_launch(void* const* d_in, const int* in_sizes, int n_in,
                              void* d_out, int out_size)
{
    const float* sf    = (const float*)d_in[0];
    const int*   sect  = (const int*)d_in[1];
    const int*   adj   = (const int*)d_in[2];
    const float* g1Wih = (const float*)d_in[3];
    const float* g1Whh = (const float*)d_in[4];
    const float* g1bih = (const float*)d_in[5];
    const float* g1bhh = (const float*)d_in[6];
    const float* a1w   = (const float*)d_in[7];
    const float* a1b   = (const float*)d_in[8];
    const float* giW   = (const float*)d_in[9];
    const float* gia   = (const float*)d_in[10];
    const float* ggWih = (const float*)d_in[11];
    const float* ggWhh = (const float*)d_in[12];
    const float* ggbih = (const float*)d_in[13];
    const float* ggbhh = (const float*)d_in[14];
    const float* agw   = (const float*)d_in[15];
    const float* agb   = (const float*)d_in[16];
    const float* gaWih = (const float*)d_in[17];
    const float* gaWhh = (const float*)d_in[18];
    const float* gabih = (const float*)d_in[19];
    const float* gabhh = (const float*)d_in[20];
    const float* aaw   = (const float*)d_in[21];
    const float* aab   = (const float*)d_in[22];
    const float* geW   = (const float*)d_in[23];
    const float* gea   = (const float*)d_in[24];
    const float* fw    = (const float*)d_in[25];
    const float* fb    = (const float*)d_in[26];
    const float* rw    = (const float*)d_in[27];
    const float* rb    = (const float*)d_in[28];
    const float* mw    = (const float*)d_in[29];
    const float* mb    = (const float*)d_in[30];
    float* out = (float*)d_out;

    float *gi, *shortb, *WB1f, *WiBf, *WB4f, *WiB4f, *intra, *lgv, *lav, *Wh, *s12, *sec, *Wh2, *s12b, *secout;
    cudaGetSymbolAddress((void**)&gi, g_gi);
    cudaGetSymbolAddress((void**)&shortb, g_short);
    cudaGetSymbolAddress((void**)&WB1f, g_WB1);
    cudaGetSymbolAddress((void**)&WiBf, g_WiB);
    cudaGetSymbolAddress((void**)&WB4f, g_WB4);
    cudaGetSymbolAddress((void**)&WiB4f, g_WiB4);
    cudaGetSymbolAddress((void**)&intra, g_intra);
    cudaGetSymbolAddress((void**)&lgv, g_lg);
    cudaGetSymbolAddress((void**)&lav, g_la);
    cudaGetSymbolAddress((void**)&Wh, g_Wh);
    cudaGetSymbolAddress((void**)&s12, g_s12);
    cudaGetSymbolAddress((void**)&sec, g_sec);
    cudaGetSymbolAddress((void**)&Wh2, g_Wh2);
    cudaGetSymbolAddress((void**)&s12b, g_s12b);
    cudaGetSymbolAddress((void**)&secout, g_secout);
    __nv_bfloat16* WB1  = (__nv_bfloat16*)WB1f;
    __nv_bfloat16* WiB  = (__nv_bfloat16*)WiBf;
    __nv_bfloat16* WB4  = (__nv_bfloat16*)WB4f;
    __nv_bfloat16* WiB4 = (__nv_bfloat16*)WiB4f;

    const int smem1 = 5 * 16 * 136 * 2 + 16 * 88 * 2 + 16 * 5 * 4;            // 24896
    const int smem4 = 384 * 136 * 2 + 2 * 16 * 136 * 2 * 2 + 2 * 256 * 4;     // 123904
    const int smemG = 2 * 64 * 136 * 2;                                       // 34816
    cudaFuncSetAttribute(gru_mma<5>,
                         cudaFuncAttributeMaxDynamicSharedMemorySize, smem1);
    cudaFuncSetAttribute(gru4_fused,
                         cudaFuncAttributeMaxDynamicSharedMemorySize, smem4);

    // weight conversions to bf16
    conv_bf16<<<(49152 + 255) / 256, 256>>>(g1Whh, WB1, 49152);
    conv_bf16<<<(6144 + 255) / 256, 256>>>(g1Wih, WiB, 6144);
    conv_bf16<<<(49152 + 255) / 256, 256>>>(gaWhh, WB4, 49152);
    conv_bf16<<<(49152 + 255) / 256, 256>>>(gaWih, WiB4, 49152);

    // Stage 1: fused GRU1 + attention over 65536 sequences (T=5, F=16), persistent
    gru_mma<5><<<148, 512, smem1>>>(
        sf, WiB, WB1, g1bih, g1bhh, a1w, a1b, shortb, 4096);

    // Stage 2: intra-sector GAT on last week's embedding
    gat_prep<<<2048, 128>>>(shortb + 31 * 128, 32 * 128, giW, gia, Wh, s12, 2048);
    gat_intra_attn<<<2048, 128>>>(Wh, s12, sect, intra);

    // Stage 3: lg = single-step GRU (h0=0, T=1 attn = identity)
    gemm_bf16<<<dim3(2048 / 64, 6), 256, smemG>>>(intra, ggWih, ggbih, gi);
    gru_single<<<1024, 256>>>(gi, ggbhh, lgv);

    // Stage 4: la = fully fused gi-MMA + GRU(T=32) + online pooling
    gru4_fused<<<128, 512, smem4>>>(
        shortb, WiB4, WB4, gabih, gabhh, aaw, aab, lav);

    // Stage 5: sector aggregation + inter-sector GAT
    sector_mean<<<16, 128>>>(lgv, sect, sec);
    gat_prep<<<16, 128>>>(sec, 128, geW, gea, Wh2, s12b, 16);
    gat_inter_attn<<<16, 128>>>(Wh2, s12b, adj, secout);

    // Stage 6: fusion + heads
    fusion_heads<<<2048, 128>>>(lgv, lav, secout, sect, fw, fb, rw, rb, mw, mb, out);
}

// round 10
// speedup vs baseline: 1.2167x; 1.2167x over previous
#include <cuda_runtime.h>
#include <cuda_bf16.h>
#include <math.h>

// ---------------- scratch (device globals; no allocation) ----------------
__device__ float g_gi[25165824];    // 65536 x 384
__device__ float g_short[8388608];  // 65536 x 128
__device__ float g_WB1[24576];      // Whh1 bf16 [384][128] (as float storage)
__device__ float g_WiB[3072];       // Wih1 bf16 [384][16]
__device__ float g_WB4[24576];      // gaWhh bf16 [384][128]
__device__ float g_intra[262144];
__device__ float g_lg[262144];
__device__ float g_la[262144];
__device__ float g_Wh[262144];
__device__ float g_s12[4096];
__device__ float g_sec[2048];
__device__ float g_Wh2[2048];
__device__ float g_s12b[32];
__device__ float g_secout[2048];

// ---------------- helpers ----------------
__device__ __forceinline__ float sigmoidf_(float x) {
    return __fdividef(1.f, 1.f + __expf(-x));
}
__device__ __forceinline__ float tanhapx_(float x) {
    float y; asm("tanh.approx.f32 %0, %1;" : "=f"(y) : "f"(x)); return y;
}
__device__ __forceinline__ float sigapx_(float x) {
    return fmaf(tanhapx_(0.5f * x), 0.5f, 0.5f);
}
__device__ __forceinline__ void mma_bf16(float d[4], unsigned a0, unsigned a1,
                                         unsigned a2, unsigned a3,
                                         unsigned b0, unsigned b1) {
    asm volatile(
        "mma.sync.aligned.m16n8k16.row.col.f32.bf16.bf16.f32 "
        "{%0,%1,%2,%3},{%4,%5,%6,%7},{%8,%9},{%0,%1,%2,%3};\n"
        : "+f"(d[0]), "+f"(d[1]), "+f"(d[2]), "+f"(d[3])
        : "r"(a0), "r"(a1), "r"(a2), "r"(a3), "r"(b0), "r"(b1));
}
__device__ __forceinline__ float blockReduceSum128(float v, float* red) {
    #pragma unroll
    for (int o = 16; o; o >>= 1) v += __shfl_xor_sync(0xffffffffu, v, o);
    int w = threadIdx.x >> 5;
    if ((threadIdx.x & 31) == 0) red[w] = v;
    __syncthreads();
    float s = red[0] + red[1] + red[2] + red[3];
    __syncthreads();
    return s;
}

// ---------------- fused fp32 -> bf16 weight conversion (one launch) ----------------
__global__ void conv_all(const float* __restrict__ W1, __nv_bfloat16* __restrict__ O1,
                         const float* __restrict__ W2, __nv_bfloat16* __restrict__ O2,
                         const float* __restrict__ W3, __nv_bfloat16* __restrict__ O3) {
    int i = blockIdx.x * 256 + threadIdx.x;
    if (i < 49152) O1[i] = __float2bfloat16(W1[i]);
    if (i < 6144)  O2[i] = __float2bfloat16(W2[i]);
    if (i < 49152) O3[i] = __float2bfloat16(W3[i]);
}

// ---------------- stage-1: dual-batch bf16 GRU + fused pooling, persistent ----------------
// Each iteration handles 32 seqs (2 batches of 16). 512 thr = 16 warps;
// warp w owns cols w*8 of each gate block for BOTH batches (weights shared).
__global__ void __launch_bounds__(512, 1) gru1_dual(
    const float* __restrict__ xin,          // x rows of 80
    const __nv_bfloat16* __restrict__ WiB,  // Wih bf16 [384][16]
    const __nv_bfloat16* __restrict__ WB,   // Whh bf16 [384][128]
    const float* __restrict__ bih, const float* __restrict__ bhh,
    const float* __restrict__ aw, const float* __restrict__ ab,
    float* __restrict__ outp,               // [seq][128] pooled
    int nPair)
{
    constexpr int T = 5;
    extern __shared__ char smc[];
    __nv_bfloat16* hsm = (__nv_bfloat16*)smc;      // [2][T][16][136]
    __nv_bfloat16* x_b = hsm + 2 * T * 16 * 136;   // [2][16][88]
    float* sc_s = (float*)(x_b + 2 * 16 * 88);     // [2][16][T]

    int tid = threadIdx.x;
    int w = tid >> 5, lane = tid & 31;
    int g = lane >> 2, tig = lane & 3;
    int c0 = w * 8 + 2 * tig;

    unsigned wb[8][3][2];
    #pragma unroll
    for (int kt = 0; kt < 8; kt++) {
        #pragma unroll
        for (int nt = 0; nt < 3; nt++) {
            const __nv_bfloat16* p = WB + (size_t)(nt * 128 + w * 8 + g) * 128 + kt * 16;
            wb[kt][nt][0] = *(const unsigned*)(p + 2 * tig);
            wb[kt][nt][1] = *(const unsigned*)(p + 8 + 2 * tig);
        }
    }
    unsigned wbi[3][2];
    #pragma unroll
    for (int nt = 0; nt < 3; nt++) {
        const __nv_bfloat16* p = WiB + (size_t)(nt * 128 + w * 8 + g) * 16;
        wbi[nt][0] = *(const unsigned*)(p + 2 * tig);
        wbi[nt][1] = *(const unsigned*)(p + 8 + 2 * tig);
    }
    // biases: r,z pre-combined (bih+bhh); n kept split
    float2 t1, t2;
    t1 = *(const float2*)(bih + c0);       t2 = *(const float2*)(bhh + c0);
    float2 br2 = make_float2(t1.x + t2.x, t1.y + t2.y);
    t1 = *(const float2*)(bih + 128 + c0); t2 = *(const float2*)(bhh + 128 + c0);
    float2 bz2 = make_float2(t1.x + t2.x, t1.y + t2.y);
    float2 bin2 = *(const float2*)(bih + 256 + c0);
    float2 bhn2 = *(const float2*)(bhh + 256 + c0);
    float ab0 = __ldg(ab);
    float awv[4];
    #pragma unroll
    for (int q = 0; q < 4; q++) awv[q] = __ldg(aw + lane + 32 * q);

    for (int b = blockIdx.x; b < nPair; b += gridDim.x) {
        size_t seq0 = (size_t)b * 32;

        // stage x for both batches: contiguous 2560 floats
        for (int i = tid; i < 2560; i += 512) {
            int u = i / 1280, rr = (i % 1280) / 80, col = i % 80;
            x_b[u * (16 * 88) + rr * 88 + col] =
                __float2bfloat16(__ldg(xin + seq0 * 80 + i));
        }
        __syncthreads();

        for (int t = 0; t < T; t++) {
            float aR[2][4] = {}, aZ[2][4] = {}, aN[2][4] = {}, aI[2][4] = {};
            // gi = x @ Wih^T (one k16 MMA per gate per batch)
            #pragma unroll
            for (int u = 0; u < 2; u++) {
                const __nv_bfloat16* xb = x_b + u * (16 * 88);
                int kc = t * 16 + 2 * tig;
                unsigned a0 = *(const unsigned*)(xb + g * 88 + kc);
                unsigned a1 = *(const unsigned*)(xb + (g + 8) * 88 + kc);
                unsigned a2 = *(const unsigned*)(xb + g * 88 + kc + 8);
                unsigned a3 = *(const unsigned*)(xb + (g + 8) * 88 + kc + 8);
                mma_bf16(aR[u], a0, a1, a2, a3, wbi[0][0], wbi[0][1]);
                mma_bf16(aZ[u], a0, a1, a2, a3, wbi[1][0], wbi[1][1]);
                mma_bf16(aI[u], a0, a1, a2, a3, wbi[2][0], wbi[2][1]);
            }
            if (t > 0) {
                #pragma unroll
                for (int kt = 0; kt < 8; kt++) {
                    #pragma unroll
                    for (int u = 0; u < 2; u++) {
                        const __nv_bfloat16* hb =
                            hsm + u * (T * 16 * 136) + (t - 1) * (16 * 136);
                        int kc = kt * 16 + 2 * tig;
                        unsigned a0 = *(const unsigned*)(hb + g * 136 + kc);
                        unsigned a1 = *(const unsigned*)(hb + (g + 8) * 136 + kc);
                        unsigned a2 = *(const unsigned*)(hb + g * 136 + kc + 8);
                        unsigned a3 = *(const unsigned*)(hb + (g + 8) * 136 + kc + 8);
                        mma_bf16(aR[u], a0, a1, a2, a3, wb[kt][0][0], wb[kt][0][1]);
                        mma_bf16(aZ[u], a0, a1, a2, a3, wb[kt][1][0], wb[kt][1][1]);
                        mma_bf16(aN[u], a0, a1, a2, a3, wb[kt][2][0], wb[kt][2][1]);
                    }
                }
            }
            // gate update
            #pragma unroll
            for (int u = 0; u < 2; u++) {
                __nv_bfloat16* hcur = hsm + u * (T * 16 * 136) + t * (16 * 136);
                const __nv_bfloat16* hprv =
                    hsm + u * (T * 16 * 136) + (t > 0 ? t - 1 : 0) * (16 * 136);
                #pragma unroll
                for (int hh = 0; hh < 2; hh++) {
                    int row = hh ? g + 8 : g;
                    int e = hh * 2;
                    float gr0 = aR[u][e] + br2.x, gr1 = aR[u][e + 1] + br2.y;
                    float gz0 = aZ[u][e] + bz2.x, gz1 = aZ[u][e + 1] + bz2.y;
                    float gn0 = aN[u][e] + bhn2.x, gn1 = aN[u][e + 1] + bhn2.y;
                    float in0 = aI[u][e] + bin2.x, in1 = aI[u][e + 1] + bin2.y;
                    float r0 = sigapx_(gr0), r1 = sigapx_(gr1);
                    float z0 = sigapx_(gz0), z1 = sigapx_(gz1);
                    float n0 = tanhapx_(fmaf(r0, gn0, in0));
                    float n1 = tanhapx_(fmaf(r1, gn1, in1));
                    float h0, h1;
                    if (t == 0) {
                        h0 = (1.f - z0) * n0;
                        h1 = (1.f - z1) * n1;
                    } else {
                        float2 hp2 = __bfloat1622float2(
                            *(const __nv_bfloat162*)(hprv + row * 136 + c0));
                        h0 = fmaf(z0, hp2.x - n0, n0);
                        h1 = fmaf(z1, hp2.y - n1, n1);
                    }
                    *(__nv_bfloat162*)(hcur + row * 136 + c0) =
                        __float22bfloat162_rn(make_float2(h0, h1));
                }
            }
            __syncthreads();
        }

        // fused attention pooling: warp w handles seq w of each batch
        #pragma unroll
        for (int u = 0; u < 2; u++) {
            const __nv_bfloat16* hb = hsm + u * (T * 16 * 136);
            for (int t = 0; t < T; t++) {
                float v = 0.f;
                #pragma unroll
                for (int q = 0; q < 4; q++)
                    v = fmaf(__bfloat162float(hb[t * (16 * 136) + w * 136 + lane + 32 * q]),
                             awv[q], v);
                #pragma unroll
                for (int o = 16; o; o >>= 1) v += __shfl_xor_sync(0xffffffffu, v, o);
                if (lane == 0) sc_s[u * (16 * T) + w * T + t] = v + ab0;
            }
        }
        __syncthreads();
        {
            int j = tid & 127, sb = tid >> 7;
            for (int q = sb; q < 32; q += 4) {
                int u = q >> 4, s = q & 15;
                const __nv_bfloat16* hb = hsm + u * (T * 16 * 136);
                const float* sc = sc_s + u * (16 * T) + s * T;
                float m = -1e30f;
                #pragma unroll
                for (int t = 0; t < T; t++) m = fmaxf(m, sc[t]);
                float Z = 0.f, acc = 0.f;
                #pragma unroll
                for (int t = 0; t < T; t++) {
                    float wt = __expf(sc[t] - m);
                    Z += wt;
                    acc = fmaf(wt, __bfloat162float(hb[t * (16 * 136) + s * 136 + j]), acc);
                }
                outp[(seq0 + u * 16 + s) * 128 + j] = acc / Z;
            }
        }
        // next iteration's leading __syncthreads protects hsm reuse
    }
}

// ---------------- stage-4: bf16 GRU over gi, fused pooling (R8 config) ----------------
__global__ void __launch_bounds__(512, 1) gru4(
    const float* __restrict__ gi,           // [(seq*32+t)][384]
    const __nv_bfloat16* __restrict__ WB,   // Whh bf16 [384][128]
    const float* __restrict__ bhh,
    const float* __restrict__ aw, const float* __restrict__ ab,
    float* __restrict__ outp)               // [2048][128]
{
    constexpr int T = 32;
    extern __shared__ char smc[];
    __nv_bfloat16* hsm = (__nv_bfloat16*)smc;   // [T][16][136]
    float* sc_s = (float*)(hsm + T * 16 * 136); // [16][T]

    int tid = threadIdx.x;
    int w = tid >> 5, lane = tid & 31;
    int g = lane >> 2, tig = lane & 3;
    int c0 = w * 8 + 2 * tig;
    size_t seq0 = (size_t)blockIdx.x * 16;

    unsigned wb[8][3][2];
    #pragma unroll
    for (int kt = 0; kt < 8; kt++) {
        #pragma unroll
        for (int nt = 0; nt < 3; nt++) {
            const __nv_bfloat16* p = WB + (size_t)(nt * 128 + w * 8 + g) * 128 + kt * 16;
            wb[kt][nt][0] = *(const unsigned*)(p + 2 * tig);
            wb[kt][nt][1] = *(const unsigned*)(p + 8 + 2 * tig);
        }
    }
    float2 bhr2 = *(const float2*)(bhh + c0);
    float2 bhz2 = *(const float2*)(bhh + 128 + c0);
    float2 bhn2 = *(const float2*)(bhh + 256 + c0);
    float ab0 = __ldg(ab);
    float awv[4];
    #pragma unroll
    for (int q = 0; q < 4; q++) awv[q] = __ldg(aw + lane + 32 * q);
    __syncthreads();

    for (int t = 0; t < T; t++) {
        float ra[4] = {0, 0, 0, 0}, rb[4] = {0, 0, 0, 0};
        float za[4] = {0, 0, 0, 0}, zb[4] = {0, 0, 0, 0};
        float na[4] = {0, 0, 0, 0}, nb[4] = {0, 0, 0, 0};
        float2 pgr[2], pgz[2], pgn[2];
        #pragma unroll
        for (int hh = 0; hh < 2; hh++) {
            int row = hh ? g + 8 : g;
            const float* gp = gi + ((seq0 + row) * (size_t)T + t) * 384;
            pgr[hh] = *(const float2*)(gp + c0);
            pgz[hh] = *(const float2*)(gp + 128 + c0);
            pgn[hh] = *(const float2*)(gp + 256 + c0);
        }
        if (t > 0) {
            const __nv_bfloat16* hb = hsm + (size_t)(t - 1) * 16 * 136;
            #pragma unroll
            for (int kt = 0; kt < 8; kt++) {
                int kc = kt * 16 + 2 * tig;
                unsigned a0 = *(const unsigned*)(hb + g * 136 + kc);
                unsigned a1 = *(const unsigned*)(hb + (g + 8) * 136 + kc);
                unsigned a2 = *(const unsigned*)(hb + g * 136 + kc + 8);
                unsigned a3 = *(const unsigned*)(hb + (g + 8) * 136 + kc + 8);
                if (kt & 1) {
                    mma_bf16(rb, a0, a1, a2, a3, wb[kt][0][0], wb[kt][0][1]);
                    mma_bf16(zb, a0, a1, a2, a3, wb[kt][1][0], wb[kt][1][1]);
                    mma_bf16(nb, a0, a1, a2, a3, wb[kt][2][0], wb[kt][2][1]);
                } else {
                    mma_bf16(ra, a0, a1, a2, a3, wb[kt][0][0], wb[kt][0][1]);
                    mma_bf16(za, a0, a1, a2, a3, wb[kt][1][0], wb[kt][1][1]);
                    mma_bf16(na, a0, a1, a2, a3, wb[kt][2][0], wb[kt][2][1]);
                }
            }
        }
        {
            __nv_bfloat16* hcur = hsm + (size_t)t * 16 * 136;
            const __nv_bfloat16* hprv = hsm + (size_t)(t > 0 ? t - 1 : 0) * 16 * 136;
            #pragma unroll
            for (int hh = 0; hh < 2; hh++) {
                int row = hh ? g + 8 : g;
                int e = hh * 2;
                float gr0 = ra[e] + rb[e] + bhr2.x + pgr[hh].x;
                float gr1 = ra[e + 1] + rb[e + 1] + bhr2.y + pgr[hh].y;
                float gz0 = za[e] + zb[e] + bhz2.x + pgz[hh].x;
                float gz1 = za[e + 1] + zb[e + 1] + bhz2.y + pgz[hh].y;
                float gn0 = na[e] + nb[e] + bhn2.x;
                float gn1 = na[e + 1] + nb[e + 1] + bhn2.y;
                float r0 = sigapx_(gr0), r1 = sigapx_(gr1);
                float z0 = sigapx_(gz0), z1 = sigapx_(gz1);
                float n0 = tanhapx_(fmaf(r0, gn0, pgn[hh].x));
                float n1 = tanhapx_(fmaf(r1, gn1, pgn[hh].y));
                float h0, h1;
                if (t == 0) {
                    h0 = (1.f - z0) * n0;
                    h1 = (1.f - z1) * n1;
                } else {
                    float2 hp2 = __bfloat1622float2(
                        *(const __nv_bfloat162*)(hprv + row * 136 + c0));
                    h0 = fmaf(z0, hp2.x - n0, n0);
                    h1 = fmaf(z1, hp2.y - n1, n1);
                }
                *(__nv_bfloat162*)(hcur + row * 136 + c0) =
                    __float22bfloat162_rn(make_float2(h0, h1));
            }
        }
        __syncthreads();
    }

    {
        int s = w;
        for (int t = 0; t < T; t++) {
            float v = 0.f;
            #pragma unroll
            for (int q = 0; q < 4; q++)
                v = fmaf(__bfloat162float(hsm[t * 16 * 136 + s * 136 + lane + 32 * q]),
                         awv[q], v);
            #pragma unroll
            for (int o = 16; o; o >>= 1) v += __shfl_xor_sync(0xffffffffu, v, o);
            if (lane == 0) sc_s[s * T + t] = v + ab0;
        }
    }
    __syncthreads();
    {
        int j = tid & 127, sb = tid >> 7;
        #pragma unroll
        for (int i = 0; i < 4; i++) {
            int s = sb + i * 4;
            float m = -1e30f;
            for (int t = 0; t < T; t++) m = fmaxf(m, sc_s[s * T + t]);
            float Z = 0.f, acc = 0.f;
            for (int t = 0; t < T; t++) {
                float wt = __expf(sc_s[s * T + t] - m);
                Z += wt;
                acc = fmaf(wt, __bfloat162float(hsm[t * 16 * 136 + s * 136 + j]), acc);
            }
            outp[(seq0 + s) * 128 + j] = acc / Z;
        }
    }
}

// ---------------- bf16 GEMM: C[M,384] = A[M,128] @ W[384,128]^T + bias ----------------
__global__ void __launch_bounds__(256) gemm_bf16(
    const float* __restrict__ A, const float* __restrict__ W,
    const float* __restrict__ bias, float* __restrict__ C)
{
    extern __shared__ char gsc[];
    __nv_bfloat16* As = (__nv_bfloat16*)gsc;  // 64 x 136
    __nv_bfloat16* Ws = As + 64 * 136;        // 64 x 136
    int tid = threadIdx.x;
    size_t m0 = (size_t)blockIdx.x * 64;
    int n0 = blockIdx.y * 64;
    for (int i = tid; i < 2048; i += 256) {
        int r = i >> 5, c4 = (i & 31) * 4;
        float4 av = *(const float4*)(A + (m0 + r) * 128 + c4);
        float4 wv = *(const float4*)(W + (size_t)(n0 + r) * 128 + c4);
        *(__nv_bfloat162*)(As + r * 136 + c4)     = __float22bfloat162_rn(make_float2(av.x, av.y));
        *(__nv_bfloat162*)(As + r * 136 + c4 + 2) = __float22bfloat162_rn(make_float2(av.z, av.w));
        *(__nv_bfloat162*)(Ws + r * 136 + c4)     = __float22bfloat162_rn(make_float2(wv.x, wv.y));
        *(__nv_bfloat162*)(Ws + r * 136 + c4 + 2) = __float22bfloat162_rn(make_float2(wv.z, wv.w));
    }
    __syncthreads();
    int w = tid >> 5, lane = tid & 31;
    int wm = w & 3, wn = w >> 2;
    int g = lane >> 2, tig = lane & 3;
    int mrow = wm * 16, nbase = wn * 32;
    float d[4][4] = {};
    #pragma unroll
    for (int k0 = 0; k0 < 128; k0 += 16) {
        int kc = k0 + 2 * tig;
        unsigned a0 = *(const unsigned*)(As + (mrow + g) * 136 + kc);
        unsigned a1 = *(const unsigned*)(As + (mrow + g + 8) * 136 + kc);
        unsigned a2 = *(const unsigned*)(As + (mrow + g) * 136 + kc + 8);
        unsigned a3 = *(const unsigned*)(As + (mrow + g + 8) * 136 + kc + 8);
        #pragma unroll
        for (int f = 0; f < 4; f++) {
            unsigned b0 = *(const unsigned*)(Ws + (nbase + f * 8 + g) * 136 + kc);
            unsigned b1 = *(const unsigned*)(Ws + (nbase + f * 8 + g) * 136 + kc + 8);
            mma_bf16(d[f], a0, a1, a2, a3, b0, b1);
        }
    }
    #pragma unroll
    for (int f = 0; f < 4; f++) {
        int col = n0 + nbase + f * 8 + 2 * tig;
        float2 b2 = *(const float2*)(bias + col);
        *(float2*)(C + (m0 + mrow + g) * 384 + col) =
            make_float2(d[f][0] + b2.x, d[f][1] + b2.y);
        *(float2*)(C + (m0 + mrow + g + 8) * 384 + col) =
            make_float2(d[f][2] + b2.x, d[f][3] + b2.y);
    }
}

// ---------------- single-step GRU with h0=0 (stage 3) ----------------
__global__ void gru_single(const float* __restrict__ gi, const float* __restrict__ bhh,
                           float* __restrict__ lg)
{
    int idx = blockIdx.x * 256 + threadIdx.x;
    int s = idx >> 7, j = idx & 127;
    const float* gp = gi + (size_t)s * 384;
    float r = sigmoidf_(__ldg(gp + j) + __ldg(bhh + j));
    float z = sigmoidf_(__ldg(gp + 128 + j) + __ldg(bhh + 128 + j));
    float n = tanhf(__ldg(gp + 256 + j) + r * __ldg(bhh + 256 + j));
    lg[idx] = (1.f - z) * n;
}

// ---------------- GAT prep ----------------
__global__ void __launch_bounds__(128) gat_prep(
    const float* __restrict__ Hin, int rstride,
    const float* __restrict__ W, const float* __restrict__ a,
    float* __restrict__ Wh, float* __restrict__ s12, int M)
{
    __shared__ float red[4];
    int m = blockIdx.x, n = threadIdx.x;
    const float* hr = Hin + (size_t)m * rstride;
    float acc = 0.f;
    #pragma unroll 8
    for (int k = 0; k < 128; k++) acc = fmaf(__ldg(hr + k), W[k * 128 + n], acc);
    Wh[(size_t)m * 128 + n] = acc;
    float s1 = blockReduceSum128(acc * __ldg(a + n), red);
    float s2 = blockReduceSum128(acc * __ldg(a + 128 + n), red);
    if (n == 0) { s12[m] = s1; s12[M + m] = s2; }
}

// ---------------- GAT intra attention ----------------
__global__ void __launch_bounds__(128) gat_intra_attn(
    const float* __restrict__ Wh, const float* __restrict__ s12,
    const int* __restrict__ sect, float* __restrict__ out)
{
    __shared__ float red[4];
    __shared__ int lst[2048];
    __shared__ float wgt[2048];
    __shared__ int cnt;
    int i = blockIdx.x, d = threadIdx.x;
    if (d == 0) cnt = 0;
    __syncthreads();
    int si = __ldg(sect + i);
    for (int j = d; j < 2048; j += 128)
        if (__ldg(sect + j) == si) { int p = atomicAdd(&cnt, 1); lst[p] = j; }
    __syncthreads();
    int n = cnt;
    float s1i = s12[i];
    float lm = -1e30f;
    for (int p = d; p < n; p += 128) {
        float e = s1i + s12[2048 + lst[p]];
        e = e >= 0.f ? e : 0.2f * e;
        lm = fmaxf(lm, e);
    }
    #pragma unroll
    for (int o = 16; o; o >>= 1) lm = fmaxf(lm, __shfl_xor_sync(0xffffffffu, lm, o));
    if ((d & 31) == 0) red[d >> 5] = lm;
    __syncthreads();
    float m = fmaxf(fmaxf(red[0], red[1]), fmaxf(red[2], red[3]));
    __syncthreads();
    float lz = 0.f;
    for (int p = d; p < n; p += 128) {
        float e = s1i + s12[2048 + lst[p]];
        e = e >= 0.f ? e : 0.2f * e;
        float w = __expf(e - m);
        wgt[p] = w;
        lz += w;
    }
    float Z = blockReduceSum128(lz, red);
    float inv = __fdividef(1.f, Z);
    float acc = 0.f;
    #pragma unroll 4
    for (int p = 0; p < n; p++) acc = fmaf(wgt[p], Wh[(size_t)lst[p] * 128 + d], acc);
    acc *= inv;
    out[(size_t)i * 128 + d] = acc > 0.f ? acc : expm1f(acc);
}

// ---------------- sector mean ----------------
__global__ void __launch_bounds__(128) sector_mean(
    const float* __restrict__ lg, const int* __restrict__ sect, float* __restrict__ sec)
{
    int ns = blockIdx.x, d = threadIdx.x;
    float s = 0.f;
    int c = 0;
    for (int i = 0; i < 2048; i++) {
        if (__ldg(sect + i) == ns) { s += lg[(size_t)i * 128 + d]; c++; }
    }
    sec[ns * 128 + d] = s / fmaxf((float)c, 1.f);
}

// ---------------- GAT inter attention ----------------
__global__ void __launch_bounds__(128) gat_inter_attn(
    const float* __restrict__ Wh, const float* __restrict__ s12,
    const int* __restrict__ adj, float* __restrict__ out)
{
    __shared__ float e[16];
    int i = blockIdx.x, d = threadIdx.x;
    if (d < 16) {
        float v = s12[i] + s12[16 + d];
        v = v >= 0.f ? v : 0.2f * v;
        e[d] = (__ldg(adj + i * 16 + d) > 0) ? v : -9.0e15f;
    }
    __syncthreads();
    float m = -1e30f;
    #pragma unroll
    for (int j = 0; j < 16; j++) m = fmaxf(m, e[j]);
    float Z = 0.f, acc = 0.f;
    #pragma unroll
    for (int j = 0; j < 16; j++) {
        float w = __expf(e[j] - m);
        Z += w;
        acc = fmaf(w, Wh[j * 128 + d], acc);
    }
    acc = __fdividef(acc, Z);
    out[i * 128 + d] = acc > 0.f ? acc : expm1f(acc);
}

// ---------------- fusion + heads ----------------
__global__ void __launch_bounds__(128) fusion_heads(
    const float* __restrict__ lg, const float* __restrict__ la,
    const float* __restrict__ secout, const int* __restrict__ sect,
    const float* __restrict__ fw, const float* __restrict__ fb,
    const float* __restrict__ rw, const float* __restrict__ rb,
    const float* __restrict__ mw, const float* __restrict__ mb,
    float* __restrict__ out)
{
    __shared__ float red[4];
    int i = blockIdx.x, n = threadIdx.x;
    int si = __ldg(sect + i);
    const float* lgr = lg + (size_t)i * 128;
    const float* lar = la + (size_t)i * 128;
    const float* ser = secout + (size_t)si * 128;
    float acc = __ldg(fb + n);
    #pragma unroll 4
    for (int k = 0; k < 128; k++) acc = fmaf(__ldg(lgr + k), fw[k * 128 + n], acc);
    #pragma unroll 4
    for (int k = 0; k < 128; k++) acc = fmaf(__ldg(lar + k), fw[(128 + k) * 128 + n], acc);
    #pragma unroll 4
    for (int k = 0; k < 128; k++) acc = fmaf(__ldg(ser + k), fw[(256 + k) * 128 + n], acc);
    float r  = blockReduceSum128(acc * __ldg(rw + n), red);
    float mv = blockReduceSum128(acc * __ldg(mw + n), red);
    if (n == 0) {
        out[i]        = r + __ldg(rb);
        out[2048 + i] = sigmoidf_(mv + __ldg(mb));
    }
}

// ---------------- launch ----------------
extern "C" void kernel_launch(void* const* d_in, const int* in_sizes, int n_in,
                              void* d_out, int out_size)
{
    const float* sf    = (const float*)d_in[0];
    const int*   sect  = (const int*)d_in[1];
    const int*   adj   = (const int*)d_in[2];
    const float* g1Wih = (const float*)d_in[3];
    const float* g1Whh = (const float*)d_in[4];
    const float* g1bih = (const float*)d_in[5];
    const float* g1bhh = (const float*)d_in[6];
    const float* a1w   = (const float*)d_in[7];
    const float* a1b   = (const float*)d_in[8];
    const float* giW   = (const float*)d_in[9];
    const float* gia   = (const float*)d_in[10];
    const float* ggWih = (const float*)d_in[11];
    const float* ggWhh = (const float*)d_in[12];
    const float* ggbih = (const float*)d_in[13];
    const float* ggbhh = (const float*)d_in[14];
    const float* agw   = (const float*)d_in[15];
    const float* agb   = (const float*)d_in[16];
    const float* gaWih = (const float*)d_in[17];
    const float* gaWhh = (const float*)d_in[18];
    const float* gabih = (const float*)d_in[19];
    const float* gabhh = (const float*)d_in[20];
    const float* aaw   = (const float*)d_in[21];
    const float* aab   = (const float*)d_in[22];
    const float* geW   = (const float*)d_in[23];
    const float* gea   = (const float*)d_in[24];
    const float* fw    = (const float*)d_in[25];
    const float* fb    = (const float*)d_in[26];
    const float* rw    = (const float*)d_in[27];
    const float* rb    = (const float*)d_in[28];
    const float* mw    = (const float*)d_in[29];
    const float* mb    = (const float*)d_in[30];
    float* out = (float*)d_out;

    float *gi, *shortb, *WB1f, *WiBf, *WB4f, *intra, *lgv, *lav, *Wh, *s12, *sec, *Wh2, *s12b, *secout;
    cudaGetSymbolAddress((void**)&gi, g_gi);
    cudaGetSymbolAddress((void**)&shortb, g_short);
    cudaGetSymbolAddress((void**)&WB1f, g_WB1);
    cudaGetSymbolAddress((void**)&WiBf, g_WiB);
    cudaGetSymbolAddress((void**)&WB4f, g_WB4);
    cudaGetSymbolAddress((void**)&intra, g_intra);
    cudaGetSymbolAddress((void**)&lgv, g_lg);
    cudaGetSymbolAddress((void**)&lav, g_la);
    cudaGetSymbolAddress((void**)&Wh, g_Wh);
    cudaGetSymbolAddress((void**)&s12, g_s12);
    cudaGetSymbolAddress((void**)&sec, g_sec);
    cudaGetSymbolAddress((void**)&Wh2, g_Wh2);
    cudaGetSymbolAddress((void**)&s12b, g_s12b);
    cudaGetSymbolAddress((void**)&secout, g_secout);
    __nv_bfloat16* WB1 = (__nv_bfloat16*)WB1f;
    __nv_bfloat16* WiB = (__nv_bfloat16*)WiBf;
    __nv_bfloat16* WB4 = (__nv_bfloat16*)WB4f;

    const int smem1 = 2 * 5 * 16 * 136 * 2 + 2 * 16 * 88 * 2 + 2 * 16 * 5 * 4;  // 49792
    const int smem4 = 32 * 16 * 136 * 2 + 16 * 32 * 4;                           // 141312
    const int smemG = 2 * 64 * 136 * 2;                                          // 34816
    cudaFuncSetAttribute(gru1_dual,
                         cudaFuncAttributeMaxDynamicSharedMemorySize, smem1);
    cudaFuncSetAttribute(gru4,
                         cudaFuncAttributeMaxDynamicSharedMemorySize, smem4);

    // fused weight conversion to bf16 (one launch)
    conv_all<<<(49152 + 255) / 256, 256>>>(g1Whh, WB1, g1Wih, WiB, gaWhh, WB4);

    // Stage 1: dual-batch fused GRU1 + attention (65536 seqs, T=5), persistent
    gru1_dual<<<148, 512, smem1>>>(
        sf, WiB, WB1, g1bih, g1bhh, a1w, a1b, shortb, 2048);

    // Stage 2: intra-sector GAT on last week's embedding
    gat_prep<<<2048, 128>>>(shortb + 31 * 128, 32 * 128, giW, gia, Wh, s12, 2048);
    gat_intra_attn<<<2048, 128>>>(Wh, s12, sect, intra);

    // Stage 3: lg = single-step GRU (h0=0, T=1 attn = identity)
    gemm_bf16<<<dim3(2048 / 64, 6), 256, smemG>>>(intra, ggWih, ggbih, gi);
    gru_single<<<1024, 256>>>(gi, ggbhh, lgv);

    // Stage 4: la = GRU over 32 weekly embeddings (T=32), pooling fused (R8 config)
    gemm_bf16<<<dim3(65536 / 64, 6), 256, smemG>>>(shortb, gaWih, gabih, gi);
    gru4<<<128, 512, smem4>>>(gi, WB4, gabhh, aaw, aab, lav);

    // Stage 5: sector aggregation + inter-sector GAT
    sector_mean<<<16, 128>>>(lgv, sect, sec);
    gat_prep<<<16, 128>>>(sec, 128, geW, gea, Wh2, s12b, 16);
    gat_inter_attn<<<16, 128>>>(Wh2, s12b, adj, secout);

    // Stage 6: fusion + heads
    fusion_heads<<<2048, 128>>>(lgv, lav, secout, sect, fw, fb, rw, rb, mw, mb, out);
}

// round 11
// speedup vs baseline: 1.5378x; 1.2640x over previous
#include <cuda_runtime.h>
#include <cuda_bf16.h>
#include <math.h>

// ---------------- scratch (device globals; no allocation) ----------------
__device__ float g_gi[25165824];    // 65536 x 384 (stage 4)
__device__ float g_gi3[786432];     // 2048 x 384 (stage 3)
__device__ float g_short[8388608];  // 65536 x 128
__device__ float g_WB1[24576];      // Whh1 bf16 [384][128] (as float storage)
__device__ float g_WiB[3072];       // Wih1 bf16 [384][16]
__device__ float g_WB4[24576];      // gaWhh bf16 [384][128]
__device__ float g_intra[262144];
__device__ float g_lg[262144];
__device__ float g_la[262144];
__device__ float g_Wh[262144];
__device__ float g_s12[4096];
__device__ float g_sec[2048];
__device__ float g_secp[32768];     // 16 sectors x 16 strips x 128
__device__ float g_cntp[256];       // 16 x 16 strip counts
__device__ float g_Wh2[2048];
__device__ float g_s12b[32];
__device__ float g_secout[2048];

// ---------------- helpers ----------------
__device__ __forceinline__ float sigmoidf_(float x) {
    return __fdividef(1.f, 1.f + __expf(-x));
}
__device__ __forceinline__ float tanhapx_(float x) {
    float y; asm("tanh.approx.f32 %0, %1;" : "=f"(y) : "f"(x)); return y;
}
__device__ __forceinline__ float sigapx_(float x) {
    return fmaf(tanhapx_(0.5f * x), 0.5f, 0.5f);
}
__device__ __forceinline__ void mma_bf16(float d[4], unsigned a0, unsigned a1,
                                         unsigned a2, unsigned a3,
                                         unsigned b0, unsigned b1) {
    asm volatile(
        "mma.sync.aligned.m16n8k16.row.col.f32.bf16.bf16.f32 "
        "{%0,%1,%2,%3},{%4,%5,%6,%7},{%8,%9},{%0,%1,%2,%3};\n"
        : "+f"(d[0]), "+f"(d[1]), "+f"(d[2]), "+f"(d[3])
        : "r"(a0), "r"(a1), "r"(a2), "r"(a3), "r"(b0), "r"(b1));
}
__device__ __forceinline__ float blockReduceSum128(float v, float* red) {
    #pragma unroll
    for (int o = 16; o; o >>= 1) v += __shfl_xor_sync(0xffffffffu, v, o);
    int w = threadIdx.x >> 5;
    if ((threadIdx.x & 31) == 0) red[w] = v;
    __syncthreads();
    float s = red[0] + red[1] + red[2] + red[3];
    __syncthreads();
    return s;
}

// ---------------- fused fp32 -> bf16 weight conversion (one launch) ----------------
__global__ void conv_all(const float* __restrict__ W1, __nv_bfloat16* __restrict__ O1,
                         const float* __restrict__ W2, __nv_bfloat16* __restrict__ O2,
                         const float* __restrict__ W3, __nv_bfloat16* __restrict__ O3) {
    int i = blockIdx.x * 256 + threadIdx.x;
    if (i < 49152) O1[i] = __float2bfloat16(W1[i]);
    if (i < 6144)  O2[i] = __float2bfloat16(W2[i]);
    if (i < 49152) O3[i] = __float2bfloat16(W3[i]);
}

// ---------------- stage-1: dual-batch bf16 GRU + fused pooling, persistent ----------------
__global__ void __launch_bounds__(512, 1) gru1_dual(
    const float* __restrict__ xin,          // x rows of 80
    const __nv_bfloat16* __restrict__ WiB,  // Wih bf16 [384][16]
    const __nv_bfloat16* __restrict__ WB,   // Whh bf16 [384][128]
    const float* __restrict__ bih, const float* __restrict__ bhh,
    const float* __restrict__ aw, const float* __restrict__ ab,
    float* __restrict__ outp,               // [seq][128] pooled
    int nPair)
{
    constexpr int T = 5;
    extern __shared__ char smc[];
    __nv_bfloat16* hsm = (__nv_bfloat16*)smc;      // [2][T][16][136]
    __nv_bfloat16* x_b = hsm + 2 * T * 16 * 136;   // [2][16][88]
    float* sc_s = (float*)(x_b + 2 * 16 * 88);     // [2][16][T]

    int tid = threadIdx.x;
    int w = tid >> 5, lane = tid & 31;
    int g = lane >> 2, tig = lane & 3;
    int c0 = w * 8 + 2 * tig;

    unsigned wb[8][3][2];
    #pragma unroll
    for (int kt = 0; kt < 8; kt++) {
        #pragma unroll
        for (int nt = 0; nt < 3; nt++) {
            const __nv_bfloat16* p = WB + (size_t)(nt * 128 + w * 8 + g) * 128 + kt * 16;
            wb[kt][nt][0] = *(const unsigned*)(p + 2 * tig);
            wb[kt][nt][1] = *(const unsigned*)(p + 8 + 2 * tig);
        }
    }
    unsigned wbi[3][2];
    #pragma unroll
    for (int nt = 0; nt < 3; nt++) {
        const __nv_bfloat16* p = WiB + (size_t)(nt * 128 + w * 8 + g) * 16;
        wbi[nt][0] = *(const unsigned*)(p + 2 * tig);
        wbi[nt][1] = *(const unsigned*)(p + 8 + 2 * tig);
    }
    float2 t1, t2;
    t1 = *(const float2*)(bih + c0);       t2 = *(const float2*)(bhh + c0);
    float2 br2 = make_float2(t1.x + t2.x, t1.y + t2.y);
    t1 = *(const float2*)(bih + 128 + c0); t2 = *(const float2*)(bhh + 128 + c0);
    float2 bz2 = make_float2(t1.x + t2.x, t1.y + t2.y);
    float2 bin2 = *(const float2*)(bih + 256 + c0);
    float2 bhn2 = *(const float2*)(bhh + 256 + c0);
    float ab0 = __ldg(ab);
    float awv[4];
    #pragma unroll
    for (int q = 0; q < 4; q++) awv[q] = __ldg(aw + lane + 32 * q);

    for (int b = blockIdx.x; b < nPair; b += gridDim.x) {
        size_t seq0 = (size_t)b * 32;

        for (int i = tid; i < 2560; i += 512) {
            int u = i / 1280, rr = (i % 1280) / 80, col = i % 80;
            x_b[u * (16 * 88) + rr * 88 + col] =
                __float2bfloat16(__ldg(xin + seq0 * 80 + i));
        }
        __syncthreads();

        for (int t = 0; t < T; t++) {
            float aR[2][4] = {}, aZ[2][4] = {}, aN[2][4] = {}, aI[2][4] = {};
            #pragma unroll
            for (int u = 0; u < 2; u++) {
                const __nv_bfloat16* xb = x_b + u * (16 * 88);
                int kc = t * 16 + 2 * tig;
                unsigned a0 = *(const unsigned*)(xb + g * 88 + kc);
                unsigned a1 = *(const unsigned*)(xb + (g + 8) * 88 + kc);
                unsigned a2 = *(const unsigned*)(xb + g * 88 + kc + 8);
                unsigned a3 = *(const unsigned*)(xb + (g + 8) * 88 + kc + 8);
                mma_bf16(aR[u], a0, a1, a2, a3, wbi[0][0], wbi[0][1]);
                mma_bf16(aZ[u], a0, a1, a2, a3, wbi[1][0], wbi[1][1]);
                mma_bf16(aI[u], a0, a1, a2, a3, wbi[2][0], wbi[2][1]);
            }
            if (t > 0) {
                #pragma unroll
                for (int kt = 0; kt < 8; kt++) {
                    #pragma unroll
                    for (int u = 0; u < 2; u++) {
                        const __nv_bfloat16* hb =
                            hsm + u * (T * 16 * 136) + (t - 1) * (16 * 136);
                        int kc = kt * 16 + 2 * tig;
                        unsigned a0 = *(const unsigned*)(hb + g * 136 + kc);
                        unsigned a1 = *(const unsigned*)(hb + (g + 8) * 136 + kc);
                        unsigned a2 = *(const unsigned*)(hb + g * 136 + kc + 8);
                        unsigned a3 = *(const unsigned*)(hb + (g + 8) * 136 + kc + 8);
                        mma_bf16(aR[u], a0, a1, a2, a3, wb[kt][0][0], wb[kt][0][1]);
                        mma_bf16(aZ[u], a0, a1, a2, a3, wb[kt][1][0], wb[kt][1][1]);
                        mma_bf16(aN[u], a0, a1, a2, a3, wb[kt][2][0], wb[kt][2][1]);
                    }
                }
            }
            #pragma unroll
            for (int u = 0; u < 2; u++) {
                __nv_bfloat16* hcur = hsm + u * (T * 16 * 136) + t * (16 * 136);
                const __nv_bfloat16* hprv =
                    hsm + u * (T * 16 * 136) + (t > 0 ? t - 1 : 0) * (16 * 136);
                #pragma unroll
                for (int hh = 0; hh < 2; hh++) {
                    int row = hh ? g + 8 : g;
                    int e = hh * 2;
                    float gr0 = aR[u][e] + br2.x, gr1 = aR[u][e + 1] + br2.y;
                    float gz0 = aZ[u][e] + bz2.x, gz1 = aZ[u][e + 1] + bz2.y;
                    float gn0 = aN[u][e] + bhn2.x, gn1 = aN[u][e + 1] + bhn2.y;
                    float in0 = aI[u][e] + bin2.x, in1 = aI[u][e + 1] + bin2.y;
                    float r0 = sigapx_(gr0), r1 = sigapx_(gr1);
                    float z0 = sigapx_(gz0), z1 = sigapx_(gz1);
                    float n0 = tanhapx_(fmaf(r0, gn0, in0));
                    float n1 = tanhapx_(fmaf(r1, gn1, in1));
                    float h0, h1;
                    if (t == 0) {
                        h0 = (1.f - z0) * n0;
                        h1 = (1.f - z1) * n1;
                    } else {
                        float2 hp2 = __bfloat1622float2(
                            *(const __nv_bfloat162*)(hprv + row * 136 + c0));
                        h0 = fmaf(z0, hp2.x - n0, n0);
                        h1 = fmaf(z1, hp2.y - n1, n1);
                    }
                    *(__nv_bfloat162*)(hcur + row * 136 + c0) =
                        __float22bfloat162_rn(make_float2(h0, h1));
                }
            }
            __syncthreads();
        }

        #pragma unroll
        for (int u = 0; u < 2; u++) {
            const __nv_bfloat16* hb = hsm + u * (T * 16 * 136);
            for (int t = 0; t < T; t++) {
                float v = 0.f;
                #pragma unroll
                for (int q = 0; q < 4; q++)
                    v = fmaf(__bfloat162float(hb[t * (16 * 136) + w * 136 + lane + 32 * q]),
                             awv[q], v);
                #pragma unroll
                for (int o = 16; o; o >>= 1) v += __shfl_xor_sync(0xffffffffu, v, o);
                if (lane == 0) sc_s[u * (16 * T) + w * T + t] = v + ab0;
            }
        }
        __syncthreads();
        {
            int j = tid & 127, sb = tid >> 7;
            for (int q = sb; q < 32; q += 4) {
                int u = q >> 4, s = q & 15;
                const __nv_bfloat16* hb = hsm + u * (T * 16 * 136);
                const float* sc = sc_s + u * (16 * T) + s * T;
                float m = -1e30f;
                #pragma unroll
                for (int t = 0; t < T; t++) m = fmaxf(m, sc[t]);
                float Z = 0.f, acc = 0.f;
                #pragma unroll
                for (int t = 0; t < T; t++) {
                    float wt = __expf(sc[t] - m);
                    Z += wt;
                    acc = fmaf(wt, __bfloat162float(hb[t * (16 * 136) + s * 136 + j]), acc);
                }
                outp[(seq0 + u * 16 + s) * 128 + j] = acc / Z;
            }
        }
    }
}

// ---------------- stage-4: bf16 GRU over gi, fused pooling ----------------
__global__ void __launch_bounds__(512, 1) gru4(
    const float* __restrict__ gi,           // [(seq*32+t)][384]
    const __nv_bfloat16* __restrict__ WB,   // Whh bf16 [384][128]
    const float* __restrict__ bhh,
    const float* __restrict__ aw, const float* __restrict__ ab,
    float* __restrict__ outp)               // [2048][128]
{
    constexpr int T = 32;
    extern __shared__ char smc[];
    __nv_bfloat16* hsm = (__nv_bfloat16*)smc;   // [T][16][136]
    float* sc_s = (float*)(hsm + T * 16 * 136); // [16][T]

    int tid = threadIdx.x;
    int w = tid >> 5, lane = tid & 31;
    int g = lane >> 2, tig = lane & 3;
    int c0 = w * 8 + 2 * tig;
    size_t seq0 = (size_t)blockIdx.x * 16;

    unsigned wb[8][3][2];
    #pragma unroll
    for (int kt = 0; kt < 8; kt++) {
        #pragma unroll
        for (int nt = 0; nt < 3; nt++) {
            const __nv_bfloat16* p = WB + (size_t)(nt * 128 + w * 8 + g) * 128 + kt * 16;
            wb[kt][nt][0] = *(const unsigned*)(p + 2 * tig);
            wb[kt][nt][1] = *(const unsigned*)(p + 8 + 2 * tig);
        }
    }
    float2 bhr2 = *(const float2*)(bhh + c0);
    float2 bhz2 = *(const float2*)(bhh + 128 + c0);
    float2 bhn2 = *(const float2*)(bhh + 256 + c0);
    float ab0 = __ldg(ab);
    float awv[4];
    #pragma unroll
    for (int q = 0; q < 4; q++) awv[q] = __ldg(aw + lane + 32 * q);
    __syncthreads();

    for (int t = 0; t < T; t++) {
        float ra[4] = {0, 0, 0, 0}, rb[4] = {0, 0, 0, 0};
        float za[4] = {0, 0, 0, 0}, zb[4] = {0, 0, 0, 0};
        float na[4] = {0, 0, 0, 0}, nb[4] = {0, 0, 0, 0};
        float2 pgr[2], pgz[2], pgn[2];
        #pragma unroll
        for (int hh = 0; hh < 2; hh++) {
            int row = hh ? g + 8 : g;
            const float* gp = gi + ((seq0 + row) * (size_t)T + t) * 384;
            pgr[hh] = *(const float2*)(gp + c0);
            pgz[hh] = *(const float2*)(gp + 128 + c0);
            pgn[hh] = *(const float2*)(gp + 256 + c0);
        }
        if (t > 0) {
            const __nv_bfloat16* hb = hsm + (size_t)(t - 1) * 16 * 136;
            #pragma unroll
            for (int kt = 0; kt < 8; kt++) {
                int kc = kt * 16 + 2 * tig;
                unsigned a0 = *(const unsigned*)(hb + g * 136 + kc);
                unsigned a1 = *(const unsigned*)(hb + (g + 8) * 136 + kc);
                unsigned a2 = *(const unsigned*)(hb + g * 136 + kc + 8);
                unsigned a3 = *(const unsigned*)(hb + (g + 8) * 136 + kc + 8);
                if (kt & 1) {
                    mma_bf16(rb, a0, a1, a2, a3, wb[kt][0][0], wb[kt][0][1]);
                    mma_bf16(zb, a0, a1, a2, a3, wb[kt][1][0], wb[kt][1][1]);
                    mma_bf16(nb, a0, a1, a2, a3, wb[kt][2][0], wb[kt][2][1]);
                } else {
                    mma_bf16(ra, a0, a1, a2, a3, wb[kt][0][0], wb[kt][0][1]);
                    mma_bf16(za, a0, a1, a2, a3, wb[kt][1][0], wb[kt][1][1]);
                    mma_bf16(na, a0, a1, a2, a3, wb[kt][2][0], wb[kt][2][1]);
                }
            }
        }
        {
            __nv_bfloat16* hcur = hsm + (size_t)t * 16 * 136;
            const __nv_bfloat16* hprv = hsm + (size_t)(t > 0 ? t - 1 : 0) * 16 * 136;
            #pragma unroll
            for (int hh = 0; hh < 2; hh++) {
                int row = hh ? g + 8 : g;
                int e = hh * 2;
                float gr0 = ra[e] + rb[e] + bhr2.x + pgr[hh].x;
                float gr1 = ra[e + 1] + rb[e + 1] + bhr2.y + pgr[hh].y;
                float gz0 = za[e] + zb[e] + bhz2.x + pgz[hh].x;
                float gz1 = za[e + 1] + zb[e + 1] + bhz2.y + pgz[hh].y;
                float gn0 = na[e] + nb[e] + bhn2.x;
                float gn1 = na[e + 1] + nb[e + 1] + bhn2.y;
                float r0 = sigapx_(gr0), r1 = sigapx_(gr1);
                float z0 = sigapx_(gz0), z1 = sigapx_(gz1);
                float n0 = tanhapx_(fmaf(r0, gn0, pgn[hh].x));
                float n1 = tanhapx_(fmaf(r1, gn1, pgn[hh].y));
                float h0, h1;
                if (t == 0) {
                    h0 = (1.f - z0) * n0;
                    h1 = (1.f - z1) * n1;
                } else {
                    float2 hp2 = __bfloat1622float2(
                        *(const __nv_bfloat162*)(hprv + row * 136 + c0));
                    h0 = fmaf(z0, hp2.x - n0, n0);
                    h1 = fmaf(z1, hp2.y - n1, n1);
                }
                *(__nv_bfloat162*)(hcur + row * 136 + c0) =
                    __float22bfloat162_rn(make_float2(h0, h1));
            }
        }
        __syncthreads();
    }

    {
        int s = w;
        for (int t = 0; t < T; t++) {
            float v = 0.f;
            #pragma unroll
            for (int q = 0; q < 4; q++)
                v = fmaf(__bfloat162float(hsm[t * 16 * 136 + s * 136 + lane + 32 * q]),
                         awv[q], v);
            #pragma unroll
            for (int o = 16; o; o >>= 1) v += __shfl_xor_sync(0xffffffffu, v, o);
            if (lane == 0) sc_s[s * T + t] = v + ab0;
        }
    }
    __syncthreads();
    {
        int j = tid & 127, sb = tid >> 7;
        #pragma unroll
        for (int i = 0; i < 4; i++) {
            int s = sb + i * 4;
            float m = -1e30f;
            for (int t = 0; t < T; t++) m = fmaxf(m, sc_s[s * T + t]);
            float Z = 0.f, acc = 0.f;
            for (int t = 0; t < T; t++) {
                float wt = __expf(sc_s[s * T + t] - m);
                Z += wt;
                acc = fmaf(wt, __bfloat162float(hsm[t * 16 * 136 + s * 136 + j]), acc);
            }
            outp[(seq0 + s) * 128 + j] = acc / Z;
        }
    }
}

// ---------------- bf16 GEMM: C[M,384] = A[M,128] @ W[384,128]^T + bias ----------------
__global__ void __launch_bounds__(256) gemm_bf16(
    const float* __restrict__ A, const float* __restrict__ W,
    const float* __restrict__ bias, float* __restrict__ C)
{
    extern __shared__ char gsc[];
    __nv_bfloat16* As = (__nv_bfloat16*)gsc;  // 64 x 136
    __nv_bfloat16* Ws = As + 64 * 136;        // 64 x 136
    int tid = threadIdx.x;
    size_t m0 = (size_t)blockIdx.x * 64;
    int n0 = blockIdx.y * 64;
    for (int i = tid; i < 2048; i += 256) {
        int r = i >> 5, c4 = (i & 31) * 4;
        float4 av = *(const float4*)(A + (m0 + r) * 128 + c4);
        float4 wv = *(const float4*)(W + (size_t)(n0 + r) * 128 + c4);
        *(__nv_bfloat162*)(As + r * 136 + c4)     = __float22bfloat162_rn(make_float2(av.x, av.y));
        *(__nv_bfloat162*)(As + r * 136 + c4 + 2) = __float22bfloat162_rn(make_float2(av.z, av.w));
        *(__nv_bfloat162*)(Ws + r * 136 + c4)     = __float22bfloat162_rn(make_float2(wv.x, wv.y));
        *(__nv_bfloat162*)(Ws + r * 136 + c4 + 2) = __float22bfloat162_rn(make_float2(wv.z, wv.w));
    }
    __syncthreads();
    int w = tid >> 5, lane = tid & 31;
    int wm = w & 3, wn = w >> 2;
    int g = lane >> 2, tig = lane & 3;
    int mrow = wm * 16, nbase = wn * 32;
    float d[4][4] = {};
    #pragma unroll
    for (int k0 = 0; k0 < 128; k0 += 16) {
        int kc = k0 + 2 * tig;
        unsigned a0 = *(const unsigned*)(As + (mrow + g) * 136 + kc);
        unsigned a1 = *(const unsigned*)(As + (mrow + g + 8) * 136 + kc);
        unsigned a2 = *(const unsigned*)(As + (mrow + g) * 136 + kc + 8);
        unsigned a3 = *(const unsigned*)(As + (mrow + g + 8) * 136 + kc + 8);
        #pragma unroll
        for (int f = 0; f < 4; f++) {
            unsigned b0 = *(const unsigned*)(Ws + (nbase + f * 8 + g) * 136 + kc);
            unsigned b1 = *(const unsigned*)(Ws + (nbase + f * 8 + g) * 136 + kc + 8);
            mma_bf16(d[f], a0, a1, a2, a3, b0, b1);
        }
    }
    #pragma unroll
    for (int f = 0; f < 4; f++) {
        int col = n0 + nbase + f * 8 + 2 * tig;
        float2 b2 = *(const float2*)(bias + col);
        *(float2*)(C + (m0 + mrow + g) * 384 + col) =
            make_float2(d[f][0] + b2.x, d[f][1] + b2.y);
        *(float2*)(C + (m0 + mrow + g + 8) * 384 + col) =
            make_float2(d[f][2] + b2.x, d[f][3] + b2.y);
    }
}

// ---------------- single-step GRU with h0=0 (stage 3) ----------------
__global__ void gru_single(const float* __restrict__ gi, const float* __restrict__ bhh,
                           float* __restrict__ lg)
{
    int idx = blockIdx.x * 256 + threadIdx.x;
    int s = idx >> 7, j = idx & 127;
    const float* gp = gi + (size_t)s * 384;
    float r = sigmoidf_(__ldg(gp + j) + __ldg(bhh + j));
    float z = sigmoidf_(__ldg(gp + 128 + j) + __ldg(bhh + 128 + j));
    float n = tanhf(__ldg(gp + 256 + j) + r * __ldg(bhh + 256 + j));
    lg[idx] = (1.f - z) * n;
}

// ---------------- sector mean: two-phase deterministic strip reduction ----------------
__global__ void __launch_bounds__(128) sector_partial(
    const float* __restrict__ lg, const int* __restrict__ sect,
    float* __restrict__ secp, float* __restrict__ cntp)
{
    int ns = blockIdx.x >> 4, strip = blockIdx.x & 15;
    int d = threadIdx.x;
    float acc = 0.f, c = 0.f;
    #pragma unroll 4
    for (int i = strip * 128; i < strip * 128 + 128; i++) {
        if (__ldg(sect + i) == ns) {
            acc += lg[(size_t)i * 128 + d];
            c += 1.f;
        }
    }
    secp[(size_t)blockIdx.x * 128 + d] = acc;
    if (d == 0) cntp[blockIdx.x] = c;
}
__global__ void __launch_bounds__(128) sector_final(
    const float* __restrict__ secp, const float* __restrict__ cntp,
    float* __restrict__ sec)
{
    int ns = blockIdx.x, d = threadIdx.x;
    float s = 0.f, c = 0.f;
    #pragma unroll
    for (int q = 0; q < 16; q++) {
        s += secp[(size_t)(ns * 16 + q) * 128 + d];
        c += __ldg(cntp + ns * 16 + q);
    }
    sec[ns * 128 + d] = s / fmaxf(c, 1.f);
}

// ---------------- GAT prep ----------------
__global__ void __launch_bounds__(128) gat_prep(
    const float* __restrict__ Hin, int rstride,
    const float* __restrict__ W, const float* __restrict__ a,
    float* __restrict__ Wh, float* __restrict__ s12, int M)
{
    __shared__ float red[4];
    int m = blockIdx.x, n = threadIdx.x;
    const float* hr = Hin + (size_t)m * rstride;
    float acc = 0.f;
    #pragma unroll 8
    for (int k = 0; k < 128; k++) acc = fmaf(__ldg(hr + k), W[k * 128 + n], acc);
    Wh[(size_t)m * 128 + n] = acc;
    float s1 = blockReduceSum128(acc * __ldg(a + n), red);
    float s2 = blockReduceSum128(acc * __ldg(a + 128 + n), red);
    if (n == 0) { s12[m] = s1; s12[M + m] = s2; }
}

// ---------------- GAT intra attention ----------------
__global__ void __launch_bounds__(128) gat_intra_attn(
    const float* __restrict__ Wh, const float* __restrict__ s12,
    const int* __restrict__ sect, float* __restrict__ out)
{
    __shared__ float red[4];
    __shared__ int lst[2048];
    __shared__ float wgt[2048];
    __shared__ int cnt;
    int i = blockIdx.x, d = threadIdx.x;
    if (d == 0) cnt = 0;
    __syncthreads();
    int si = __ldg(sect + i);
    for (int j = d; j < 2048; j += 128)
        if (__ldg(sect + j) == si) { int p = atomicAdd(&cnt, 1); lst[p] = j; }
    __syncthreads();
    int n = cnt;
    float s1i = s12[i];
    float lm = -1e30f;
    for (int p = d; p < n; p += 128) {
        float e = s1i + s12[2048 + lst[p]];
        e = e >= 0.f ? e : 0.2f * e;
        lm = fmaxf(lm, e);
    }
    #pragma unroll
    for (int o = 16; o; o >>= 1) lm = fmaxf(lm, __shfl_xor_sync(0xffffffffu, lm, o));
    if ((d & 31) == 0) red[d >> 5] = lm;
    __syncthreads();
    float m = fmaxf(fmaxf(red[0], red[1]), fmaxf(red[2], red[3]));
    __syncthreads();
    float lz = 0.f;
    for (int p = d; p < n; p += 128) {
        float e = s1i + s12[2048 + lst[p]];
        e = e >= 0.f ? e : 0.2f * e;
        float w = __expf(e - m);
        wgt[p] = w;
        lz += w;
    }
    float Z = blockReduceSum128(lz, red);
    float inv = __fdividef(1.f, Z);
    float acc = 0.f;
    #pragma unroll 4
    for (int p = 0; p < n; p++) acc = fmaf(wgt[p], Wh[(size_t)lst[p] * 128 + d], acc);
    acc *= inv;
    out[(size_t)i * 128 + d] = acc > 0.f ? acc : expm1f(acc);
}

// ---------------- GAT inter attention ----------------
__global__ void __launch_bounds__(128) gat_inter_attn(
    const float* __restrict__ Wh, const float* __restrict__ s12,
    const int* __restrict__ adj, float* __restrict__ out)
{
    __shared__ float e[16];
    int i = blockIdx.x, d = threadIdx.x;
    if (d < 16) {
        float v = s12[i] + s12[16 + d];
        v = v >= 0.f ? v : 0.2f * v;
        e[d] = (__ldg(adj + i * 16 + d) > 0) ? v : -9.0e15f;
    }
    __syncthreads();
    float m = -1e30f;
    #pragma unroll
    for (int j = 0; j < 16; j++) m = fmaxf(m, e[j]);
    float Z = 0.f, acc = 0.f;
    #pragma unroll
    for (int j = 0; j < 16; j++) {
        float w = __expf(e[j] - m);
        Z += w;
        acc = fmaf(w, Wh[j * 128 + d], acc);
    }
    acc = __fdividef(acc, Z);
    out[i * 128 + d] = acc > 0.f ? acc : expm1f(acc);
}

// ---------------- fusion + heads ----------------
__global__ void __launch_bounds__(128) fusion_heads(
    const float* __restrict__ lg, const float* __restrict__ la,
    const float* __restrict__ secout, const int* __restrict__ sect,
    const float* __restrict__ fw, const float* __restrict__ fb,
    const float* __restrict__ rw, const float* __restrict__ rb,
    const float* __restrict__ mw, const float* __restrict__ mb,
    float* __restrict__ out)
{
    __shared__ float red[4];
    int i = blockIdx.x, n = threadIdx.x;
    int si = __ldg(sect + i);
    const float* lgr = lg + (size_t)i * 128;
    const float* lar = la + (size_t)i * 128;
    const float* ser = secout + (size_t)si * 128;
    float acc = __ldg(fb + n);
    #pragma unroll 4
    for (int k = 0; k < 128; k++) acc = fmaf(__ldg(lgr + k), fw[k * 128 + n], acc);
    #pragma unroll 4
    for (int k = 0; k < 128; k++) acc = fmaf(__ldg(lar + k), fw[(128 + k) * 128 + n], acc);
    #pragma unroll 4
    for (int k = 0; k < 128; k++) acc = fmaf(__ldg(ser + k), fw[(256 + k) * 128 + n], acc);
    float r  = blockReduceSum128(acc * __ldg(rw + n), red);
    float mv = blockReduceSum128(acc * __ldg(mw + n), red);
    if (n == 0) {
        out[i]        = r + __ldg(rb);
        out[2048 + i] = sigmoidf_(mv + __ldg(mb));
    }
}

// ---------------- launch ----------------
extern "C" void kernel_launch(void* const* d_in, const int* in_sizes, int n_in,
                              void* d_out, int out_size)
{
    const float* sf    = (const float*)d_in[0];
    const int*   sect  = (const int*)d_in[1];
    const int*   adj   = (const int*)d_in[2];
    const float* g1Wih = (const float*)d_in[3];
    const float* g1Whh = (const float*)d_in[4];
    const float* g1bih = (const float*)d_in[5];
    const float* g1bhh = (const float*)d_in[6];
    const float* a1w   = (const float*)d_in[7];
    const float* a1b   = (const float*)d_in[8];
    const float* giW   = (const float*)d_in[9];
    const float* gia   = (const float*)d_in[10];
    const float* ggWih = (const float*)d_in[11];
    const float* ggWhh = (const float*)d_in[12];
    const float* ggbih = (const float*)d_in[13];
    const float* ggbhh = (const float*)d_in[14];
    const float* agw   = (const float*)d_in[15];
    const float* agb   = (const float*)d_in[16];
    const float* gaWih = (const float*)d_in[17];
    const float* gaWhh = (const float*)d_in[18];
    const float* gabih = (const float*)d_in[19];
    const float* gabhh = (const float*)d_in[20];
    const float* aaw   = (const float*)d_in[21];
    const float* aab   = (const float*)d_in[22];
    const float* geW   = (const float*)d_in[23];
    const float* gea   = (const float*)d_in[24];
    const float* fw    = (const float*)d_in[25];
    const float* fb    = (const float*)d_in[26];
    const float* rw    = (const float*)d_in[27];
    const float* rb    = (const float*)d_in[28];
    const float* mw    = (const float*)d_in[29];
    const float* mb    = (const float*)d_in[30];
    float* out = (float*)d_out;

    float *gi, *gi3, *shortb, *WB1f, *WiBf, *WB4f, *intra, *lgv, *lav, *Wh, *s12,
          *sec, *secp, *cntp, *Wh2, *s12b, *secout;
    cudaGetSymbolAddress((void**)&gi, g_gi);
    cudaGetSymbolAddress((void**)&gi3, g_gi3);
    cudaGetSymbolAddress((void**)&shortb, g_short);
    cudaGetSymbolAddress((void**)&WB1f, g_WB1);
    cudaGetSymbolAddress((void**)&WiBf, g_WiB);
    cudaGetSymbolAddress((void**)&WB4f, g_WB4);
    cudaGetSymbolAddress((void**)&intra, g_intra);
    cudaGetSymbolAddress((void**)&lgv, g_lg);
    cudaGetSymbolAddress((void**)&lav, g_la);
    cudaGetSymbolAddress((void**)&Wh, g_Wh);
    cudaGetSymbolAddress((void**)&s12, g_s12);
    cudaGetSymbolAddress((void**)&sec, g_sec);
    cudaGetSymbolAddress((void**)&secp, g_secp);
    cudaGetSymbolAddress((void**)&cntp, g_cntp);
    cudaGetSymbolAddress((void**)&Wh2, g_Wh2);
    cudaGetSymbolAddress((void**)&s12b, g_s12b);
    cudaGetSymbolAddress((void**)&secout, g_secout);
    __nv_bfloat16* WB1 = (__nv_bfloat16*)WB1f;
    __nv_bfloat16* WiB = (__nv_bfloat16*)WiBf;
    __nv_bfloat16* WB4 = (__nv_bfloat16*)WB4f;

    // lazy one-time stream/event creation (first call is outside graph capture)
    static cudaStream_t sB = nullptr;
    static cudaEvent_t evFork = nullptr, evJoin = nullptr;
    if (!sB) {
        cudaStreamCreate(&sB);
        cudaEventCreateWithFlags(&evFork, cudaEventDisableTiming);
        cudaEventCreateWithFlags(&evJoin, cudaEventDisableTiming);
    }

    const int smem1 = 2 * 5 * 16 * 136 * 2 + 2 * 16 * 88 * 2 + 2 * 16 * 5 * 4;  // 49792
    const int smem4 = 32 * 16 * 136 * 2 + 16 * 32 * 4;                           // 141312
    const int smemG = 2 * 64 * 136 * 2;                                          // 34816
    cudaFuncSetAttribute(gru1_dual,
                         cudaFuncAttributeMaxDynamicSharedMemorySize, smem1);
    cudaFuncSetAttribute(gru4,
                         cudaFuncAttributeMaxDynamicSharedMemorySize, smem4);

    // weight conversion + Stage 1 (stream 0)
    conv_all<<<(49152 + 255) / 256, 256>>>(g1Whh, WB1, g1Wih, WiB, gaWhh, WB4);
    gru1_dual<<<148, 512, smem1>>>(
        sf, WiB, WB1, g1bih, g1bhh, a1w, a1b, shortb, 2048);

    // fork: chain B (stage 4) on stream sB, concurrent with chain A on stream 0
    cudaEventRecord(evFork, 0);
    cudaStreamWaitEvent(sB, evFork, 0);
    gemm_bf16<<<dim3(65536 / 64, 6), 256, smemG, sB>>>(shortb, gaWih, gabih, gi);
    gru4<<<128, 512, smem4, sB>>>(gi, WB4, gabhh, aaw, aab, lav);
    cudaEventRecord(evJoin, sB);

    // chain A (stream 0): intra GAT -> stage 3 -> sector -> inter GAT
    gat_prep<<<2048, 128>>>(shortb + 31 * 128, 32 * 128, giW, gia, Wh, s12, 2048);
    gat_intra_attn<<<2048, 128>>>(Wh, s12, sect, intra);
    gemm_bf16<<<dim3(2048 / 64, 6), 256, smemG>>>(intra, ggWih, ggbih, gi3);
    gru_single<<<1024, 256>>>(gi3, ggbhh, lgv);
    sector_partial<<<256, 128>>>(lgv, sect, secp, cntp);
    sector_final<<<16, 128>>>(secp, cntp, sec);
    gat_prep<<<16, 128>>>(sec, 128, geW, gea, Wh2, s12b, 16);
    gat_inter_attn<<<16, 128>>>(Wh2, s12b, adj, secout);

    // join: fusion needs both chains
    cudaStreamWaitEvent(0, evJoin, 0);
    fusion_heads<<<2048, 128>>>(lgv, lav, secout, sect, fw, fb, rw, rb, mw, mb, out);
}

// round 14
// speedup vs baseline: 1.6446x; 1.0694x over previous
#include <cuda_runtime.h>
#include <cuda_bf16.h>
#include <cuda_fp16.h>
#include <math.h>

// ---------------- scratch (device globals; no allocation) ----------------
__device__ float g_gi[12582912];    // 65536 x 384 fp16 (as float storage /2)
__device__ float g_gi3[786432];     // 2048 x 384 fp32 (stage 3)
__device__ float g_short[8388608];  // 65536 x 128
__device__ float g_WB1[24576];      // Whh1 bf16 [384][128] (as float storage)
__device__ float g_WiB[3072];       // Wih1 bf16 [384][16]
__device__ float g_WB4[24576];      // gaWhh bf16 [384][128]
__device__ float g_intra[262144];
__device__ float g_lg[262144];
__device__ float g_la[262144];
__device__ float g_Wh[262144];
__device__ float g_s12[4096];
__device__ float g_sec[2048];
__device__ float g_secp[32768];     // 16 sectors x 16 strips x 128
__device__ float g_cntp[256];
__device__ float g_Wh2[2048];
__device__ float g_s12b[32];
__device__ float g_secout[2048];

// ---------------- helpers ----------------
__device__ __forceinline__ float sigmoidf_(float x) {
    return __fdividef(1.f, 1.f + __expf(-x));
}
__device__ __forceinline__ float tanhapx_(float x) {
    float y; asm("tanh.approx.f32 %0, %1;" : "=f"(y) : "f"(x)); return y;
}
__device__ __forceinline__ float sigapx_(float x) {
    return fmaf(tanhapx_(0.5f * x), 0.5f, 0.5f);
}
__device__ __forceinline__ void mma_bf16(float d[4], unsigned a0, unsigned a1,
                                         unsigned a2, unsigned a3,
                                         unsigned b0, unsigned b1) {
    asm volatile(
        "mma.sync.aligned.m16n8k16.row.col.f32.bf16.bf16.f32 "
        "{%0,%1,%2,%3},{%4,%5,%6,%7},{%8,%9},{%0,%1,%2,%3};\n"
        : "+f"(d[0]), "+f"(d[1]), "+f"(d[2]), "+f"(d[3])
        : "r"(a0), "r"(a1), "r"(a2), "r"(a3), "r"(b0), "r"(b1));
}
__device__ __forceinline__ float blockReduceSum128(float v, float* red) {
    #pragma unroll
    for (int o = 16; o; o >>= 1) v += __shfl_xor_sync(0xffffffffu, v, o);
    int w = threadIdx.x >> 5;
    if ((threadIdx.x & 31) == 0) red[w] = v;
    __syncthreads();
    float s = red[0] + red[1] + red[2] + red[3];
    __syncthreads();
    return s;
}

// ---------------- fused fp32 -> bf16 weight conversion (one launch) ----------------
__global__ void conv_all(const float* __restrict__ W1, __nv_bfloat16* __restrict__ O1,
                         const float* __restrict__ W2, __nv_bfloat16* __restrict__ O2,
                         const float* __restrict__ W3, __nv_bfloat16* __restrict__ O3) {
    int i = blockIdx.x * 256 + threadIdx.x;
    if (i < 49152) O1[i] = __float2bfloat16(W1[i]);
    if (i < 6144)  O2[i] = __float2bfloat16(W2[i]);
    if (i < 49152) O3[i] = __float2bfloat16(W3[i]);
}

// ---------------- stage-1: dual-batch bf16 GRU + fused pooling, persistent ----------------
// x double-buffered via register prefetch (next pair's LDGs issued before pooling).
__global__ void __launch_bounds__(512, 1) gru1_dual(
    const float* __restrict__ xin,          // x rows of 80
    const __nv_bfloat16* __restrict__ WiB,  // Wih bf16 [384][16]
    const __nv_bfloat16* __restrict__ WB,   // Whh bf16 [384][128]
    const float* __restrict__ bih, const float* __restrict__ bhh,
    const float* __restrict__ aw, const float* __restrict__ ab,
    float* __restrict__ outp,               // [seq][128] pooled
    int nPair)
{
    constexpr int T = 5;
    extern __shared__ char smc[];
    __nv_bfloat16* hsm = (__nv_bfloat16*)smc;      // [2][T][16][136]
    __nv_bfloat16* x_b = hsm + 2 * T * 16 * 136;   // [2][16][88]
    float* sc_s = (float*)(x_b + 2 * 16 * 88);     // [2][16][T]

    int tid = threadIdx.x;
    int w = tid >> 5, lane = tid & 31;
    int g = lane >> 2, tig = lane & 3;
    int c0 = w * 8 + 2 * tig;

    unsigned wb[8][3][2];
    #pragma unroll
    for (int kt = 0; kt < 8; kt++) {
        #pragma unroll
        for (int nt = 0; nt < 3; nt++) {
            const __nv_bfloat16* p = WB + (size_t)(nt * 128 + w * 8 + g) * 128 + kt * 16;
            wb[kt][nt][0] = *(const unsigned*)(p + 2 * tig);
            wb[kt][nt][1] = *(const unsigned*)(p + 8 + 2 * tig);
        }
    }
    unsigned wbi[3][2];
    #pragma unroll
    for (int nt = 0; nt < 3; nt++) {
        const __nv_bfloat16* p = WiB + (size_t)(nt * 128 + w * 8 + g) * 16;
        wbi[nt][0] = *(const unsigned*)(p + 2 * tig);
        wbi[nt][1] = *(const unsigned*)(p + 8 + 2 * tig);
    }
    float2 t1, t2;
    t1 = *(const float2*)(bih + c0);       t2 = *(const float2*)(bhh + c0);
    float2 br2 = make_float2(t1.x + t2.x, t1.y + t2.y);
    t1 = *(const float2*)(bih + 128 + c0); t2 = *(const float2*)(bhh + 128 + c0);
    float2 bz2 = make_float2(t1.x + t2.x, t1.y + t2.y);
    float2 bin2 = *(const float2*)(bih + 256 + c0);
    float2 bhn2 = *(const float2*)(bhh + 256 + c0);
    float ab0 = __ldg(ab);
    float awv[4];
    #pragma unroll
    for (int q = 0; q < 4; q++) awv[q] = __ldg(aw + lane + 32 * q);

    // x_b element indices for this thread (5 elements: tid + q*512)
    float xf[5];
    bool have_pf = false;

    for (int b = blockIdx.x; b < nPair; b += gridDim.x) {
        size_t seq0 = (size_t)b * 32;

        if (!have_pf) {
            for (int i = tid; i < 2560; i += 512) {
                int u = i / 1280, rr = (i % 1280) / 80, col = i % 80;
                x_b[u * (16 * 88) + rr * 88 + col] =
                    __float2bfloat16(__ldg(xin + seq0 * 80 + i));
            }
        } else {
            #pragma unroll
            for (int q = 0; q < 5; q++) {
                int i = tid + q * 512;
                int u = i / 1280, rr = (i % 1280) / 80, col = i % 80;
                x_b[u * (16 * 88) + rr * 88 + col] = __float2bfloat16(xf[q]);
            }
        }
        __syncthreads();

        for (int t = 0; t < T; t++) {
            float aR[2][4] = {}, aZ[2][4] = {}, aN[2][4] = {}, aI[2][4] = {};
            #pragma unroll
            for (int u = 0; u < 2; u++) {
                const __nv_bfloat16* xb = x_b + u * (16 * 88);
                int kc = t * 16 + 2 * tig;
                unsigned a0 = *(const unsigned*)(xb + g * 88 + kc);
                unsigned a1 = *(const unsigned*)(xb + (g + 8) * 88 + kc);
                unsigned a2 = *(const unsigned*)(xb + g * 88 + kc + 8);
                unsigned a3 = *(const unsigned*)(xb + (g + 8) * 88 + kc + 8);
                mma_bf16(aR[u], a0, a1, a2, a3, wbi[0][0], wbi[0][1]);
                mma_bf16(aZ[u], a0, a1, a2, a3, wbi[1][0], wbi[1][1]);
                mma_bf16(aI[u], a0, a1, a2, a3, wbi[2][0], wbi[2][1]);
            }
            if (t > 0) {
                #pragma unroll
                for (int kt = 0; kt < 8; kt++) {
                    #pragma unroll
                    for (int u = 0; u < 2; u++) {
                        const __nv_bfloat16* hb =
                            hsm + u * (T * 16 * 136) + (t - 1) * (16 * 136);
                        int kc = kt * 16 + 2 * tig;
                        unsigned a0 = *(const unsigned*)(hb + g * 136 + kc);
                        unsigned a1 = *(const unsigned*)(hb + (g + 8) * 136 + kc);
                        unsigned a2 = *(const unsigned*)(hb + g * 136 + kc + 8);
                        unsigned a3 = *(const unsigned*)(hb + (g + 8) * 136 + kc + 8);
                        mma_bf16(aR[u], a0, a1, a2, a3, wb[kt][0][0], wb[kt][0][1]);
                        mma_bf16(aZ[u], a0, a1, a2, a3, wb[kt][1][0], wb[kt][1][1]);
                        mma_bf16(aN[u], a0, a1, a2, a3, wb[kt][2][0], wb[kt][2][1]);
                    }
                }
            }
            #pragma unroll
            for (int u = 0; u < 2; u++) {
                __nv_bfloat16* hcur = hsm + u * (T * 16 * 136) + t * (16 * 136);
                const __nv_bfloat16* hprv =
                    hsm + u * (T * 16 * 136) + (t > 0 ? t - 1 : 0) * (16 * 136);
                #pragma unroll
                for (int hh = 0; hh < 2; hh++) {
                    int row = hh ? g + 8 : g;
                    int e = hh * 2;
                    float gr0 = aR[u][e] + br2.x, gr1 = aR[u][e + 1] + br2.y;
                    float gz0 = aZ[u][e] + bz2.x, gz1 = aZ[u][e + 1] + bz2.y;
                    float gn0 = aN[u][e] + bhn2.x, gn1 = aN[u][e + 1] + bhn2.y;
                    float in0 = aI[u][e] + bin2.x, in1 = aI[u][e + 1] + bin2.y;
                    float r0 = sigapx_(gr0), r1 = sigapx_(gr1);
                    float z0 = sigapx_(gz0), z1 = sigapx_(gz1);
                    float n0 = tanhapx_(fmaf(r0, gn0, in0));
                    float n1 = tanhapx_(fmaf(r1, gn1, in1));
                    float h0, h1;
                    if (t == 0) {
                        h0 = (1.f - z0) * n0;
                        h1 = (1.f - z1) * n1;
                    } else {
                        float2 hp2 = __bfloat1622float2(
                            *(const __nv_bfloat162*)(hprv + row * 136 + c0));
                        h0 = fmaf(z0, hp2.x - n0, n0);
                        h1 = fmaf(z1, hp2.y - n1, n1);
                    }
                    *(__nv_bfloat162*)(hcur + row * 136 + c0) =
                        __float22bfloat162_rn(make_float2(h0, h1));
                }
            }
            __syncthreads();
        }

        // prefetch next pair's x while pooling runs
        {
            int bn = b + gridDim.x;
            if (bn < nPair) {
                const float* xp = xin + (size_t)bn * 32 * 80;
                #pragma unroll
                for (int q = 0; q < 5; q++) xf[q] = __ldg(xp + tid + q * 512);
                have_pf = true;
            } else {
                have_pf = false;
            }
        }

        #pragma unroll
        for (int u = 0; u < 2; u++) {
            const __nv_bfloat16* hb = hsm + u * (T * 16 * 136);
            for (int t = 0; t < T; t++) {
                float v = 0.f;
                #pragma unroll
                for (int q = 0; q < 4; q++)
                    v = fmaf(__bfloat162float(hb[t * (16 * 136) + w * 136 + lane + 32 * q]),
                             awv[q], v);
                #pragma unroll
                for (int o = 16; o; o >>= 1) v += __shfl_xor_sync(0xffffffffu, v, o);
                if (lane == 0) sc_s[u * (16 * T) + w * T + t] = v + ab0;
            }
        }
        __syncthreads();
        {
            int j = tid & 127, sb = tid >> 7;
            for (int q = sb; q < 32; q += 4) {
                int u = q >> 4, s = q & 15;
                const __nv_bfloat16* hb = hsm + u * (T * 16 * 136);
                const float* sc = sc_s + u * (16 * T) + s * T;
                float m = -1e30f;
                #pragma unroll
                for (int t = 0; t < T; t++) m = fmaxf(m, sc[t]);
                float Z = 0.f, acc = 0.f;
                #pragma unroll
                for (int t = 0; t < T; t++) {
                    float wt = __expf(sc[t] - m);
                    Z += wt;
                    acc = fmaf(wt, __bfloat162float(hb[t * (16 * 136) + s * 136 + j]), acc);
                }
                outp[(seq0 + u * 16 + s) * 128 + j] = acc / Z;
            }
        }
        // next iteration's leading __syncthreads (after x_b write) protects hsm reuse
    }
}

// ---------------- stage-4: bf16 GRU over fp16 gi, fused pooling ----------------
__global__ void __launch_bounds__(512, 1) gru4(
    const __half* __restrict__ gi,          // [(seq*32+t)][384] fp16
    const __nv_bfloat16* __restrict__ WB,   // Whh bf16 [384][128]
    const float* __restrict__ bhh,
    const float* __restrict__ aw, const float* __restrict__ ab,
    float* __restrict__ outp)               // [2048][128]
{
    constexpr int T = 32;
    extern __shared__ char smc[];
    __nv_bfloat16* hsm = (__nv_bfloat16*)smc;   // [T][16][136]
    float* sc_s = (float*)(hsm + T * 16 * 136); // [16][T]

    int tid = threadIdx.x;
    int w = tid >> 5, lane = tid & 31;
    int g = lane >> 2, tig = lane & 3;
    int c0 = w * 8 + 2 * tig;
    size_t seq0 = (size_t)blockIdx.x * 16;

    unsigned wb[8][3][2];
    #pragma unroll
    for (int kt = 0; kt < 8; kt++) {
        #pragma unroll
        for (int nt = 0; nt < 3; nt++) {
            const __nv_bfloat16* p = WB + (size_t)(nt * 128 + w * 8 + g) * 128 + kt * 16;
            wb[kt][nt][0] = *(const unsigned*)(p + 2 * tig);
            wb[kt][nt][1] = *(const unsigned*)(p + 8 + 2 * tig);
        }
    }
    float2 bhr2 = *(const float2*)(bhh + c0);
    float2 bhz2 = *(const float2*)(bhh + 128 + c0);
    float2 bhn2 = *(const float2*)(bhh + 256 + c0);
    float ab0 = __ldg(ab);
    float awv[4];
    #pragma unroll
    for (int q = 0; q < 4; q++) awv[q] = __ldg(aw + lane + 32 * q);
    __syncthreads();

    for (int t = 0; t < T; t++) {
        float ra[4] = {0, 0, 0, 0}, rb[4] = {0, 0, 0, 0};
        float za[4] = {0, 0, 0, 0}, zb[4] = {0, 0, 0, 0};
        float na[4] = {0, 0, 0, 0}, nb[4] = {0, 0, 0, 0};
        float2 pgr[2], pgz[2], pgn[2];
        #pragma unroll
        for (int hh = 0; hh < 2; hh++) {
            int row = hh ? g + 8 : g;
            const __half* gp = gi + ((seq0 + row) * (size_t)T + t) * 384;
            pgr[hh] = __half22float2(*(const __half2*)(gp + c0));
            pgz[hh] = __half22float2(*(const __half2*)(gp + 128 + c0));
            pgn[hh] = __half22float2(*(const __half2*)(gp + 256 + c0));
        }
        if (t > 0) {
            const __nv_bfloat16* hb = hsm + (size_t)(t - 1) * 16 * 136;
            #pragma unroll
            for (int kt = 0; kt < 8; kt++) {
                int kc = kt * 16 + 2 * tig;
                unsigned a0 = *(const unsigned*)(hb + g * 136 + kc);
                unsigned a1 = *(const unsigned*)(hb + (g + 8) * 136 + kc);
                unsigned a2 = *(const unsigned*)(hb + g * 136 + kc + 8);
                unsigned a3 = *(const unsigned*)(hb + (g + 8) * 136 + kc + 8);
                if (kt & 1) {
                    mma_bf16(rb, a0, a1, a2, a3, wb[kt][0][0], wb[kt][0][1]);
                    mma_bf16(zb, a0, a1, a2, a3, wb[kt][1][0], wb[kt][1][1]);
                    mma_bf16(nb, a0, a1, a2, a3, wb[kt][2][0], wb[kt][2][1]);
                } else {
                    mma_bf16(ra, a0, a1, a2, a3, wb[kt][0][0], wb[kt][0][1]);
                    mma_bf16(za, a0, a1, a2, a3, wb[kt][1][0], wb[kt][1][1]);
                    mma_bf16(na, a0, a1, a2, a3, wb[kt][2][0], wb[kt][2][1]);
                }
            }
        }
        {
            __nv_bfloat16* hcur = hsm + (size_t)t * 16 * 136;
            const __nv_bfloat16* hprv = hsm + (size_t)(t > 0 ? t - 1 : 0) * 16 * 136;
            #pragma unroll
            for (int hh = 0; hh < 2; hh++) {
                int row = hh ? g + 8 : g;
                int e = hh * 2;
                float gr0 = ra[e] + rb[e] + bhr2.x + pgr[hh].x;
                float gr1 = ra[e + 1] + rb[e + 1] + bhr2.y + pgr[hh].y;
                float gz0 = za[e] + zb[e] + bhz2.x + pgz[hh].x;
                float gz1 = za[e + 1] + zb[e + 1] + bhz2.y + pgz[hh].y;
                float gn0 = na[e] + nb[e] + bhn2.x;
                float gn1 = na[e + 1] + nb[e + 1] + bhn2.y;
                float r0 = sigapx_(gr0), r1 = sigapx_(gr1);
                float z0 = sigapx_(gz0), z1 = sigapx_(gz1);
                float n0 = tanhapx_(fmaf(r0, gn0, pgn[hh].x));
                float n1 = tanhapx_(fmaf(r1, gn1, pgn[hh].y));
                float h0, h1;
                if (t == 0) {
                    h0 = (1.f - z0) * n0;
                    h1 = (1.f - z1) * n1;
                } else {
                    float2 hp2 = __bfloat1622float2(
                        *(const __nv_bfloat162*)(hprv + row * 136 + c0));
                    h0 = fmaf(z0, hp2.x - n0, n0);
                    h1 = fmaf(z1, hp2.y - n1, n1);
                }
                *(__nv_bfloat162*)(hcur + row * 136 + c0) =
                    __float22bfloat162_rn(make_float2(h0, h1));
            }
        }
        __syncthreads();
    }

    {
        int s = w;
        for (int t = 0; t < T; t++) {
            float v = 0.f;
            #pragma unroll
            for (int q = 0; q < 4; q++)
                v = fmaf(__bfloat162float(hsm[t * 16 * 136 + s * 136 + lane + 32 * q]),
                         awv[q], v);
            #pragma unroll
            for (int o = 16; o; o >>= 1) v += __shfl_xor_sync(0xffffffffu, v, o);
            if (lane == 0) sc_s[s * T + t] = v + ab0;
        }
    }
    __syncthreads();
    {
        int j = tid & 127, sb = tid >> 7;
        #pragma unroll
        for (int i = 0; i < 4; i++) {
            int s = sb + i * 4;
            float m = -1e30f;
            for (int t = 0; t < T; t++) m = fmaxf(m, sc_s[s * T + t]);
            float Z = 0.f, acc = 0.f;
            for (int t = 0; t < T; t++) {
                float wt = __expf(sc_s[s * T + t] - m);
                Z += wt;
                acc = fmaf(wt, __bfloat162float(hsm[t * 16 * 136 + s * 136 + j]), acc);
            }
            outp[(seq0 + s) * 128 + j] = acc / Z;
        }
    }
}

// ---------------- bf16 GEMM: C[M,384] = A[M,128] @ W[384,128]^T + bias ----------------
// OutT = float (stage 3) or __half (stage 4 gi).
template<typename OutT>
__global__ void __launch_bounds__(256) gemm_bf16(
    const float* __restrict__ A, const float* __restrict__ W,
    const float* __restrict__ bias, OutT* __restrict__ C)
{
    extern __shared__ char gsc[];
    __nv_bfloat16* As = (__nv_bfloat16*)gsc;  // 64 x 136
    __nv_bfloat16* Ws = As + 64 * 136;        // 64 x 136
    int tid = threadIdx.x;
    size_t m0 = (size_t)blockIdx.x * 64;
    int n0 = blockIdx.y * 64;
    for (int i = tid; i < 2048; i += 256) {
        int r = i >> 5, c4 = (i & 31) * 4;
        float4 av = *(const float4*)(A + (m0 + r) * 128 + c4);
        float4 wv = *(const float4*)(W + (size_t)(n0 + r) * 128 + c4);
        *(__nv_bfloat162*)(As + r * 136 + c4)     = __float22bfloat162_rn(make_float2(av.x, av.y));
        *(__nv_bfloat162*)(As + r * 136 + c4 + 2) = __float22bfloat162_rn(make_float2(av.z, av.w));
        *(__nv_bfloat162*)(Ws + r * 136 + c4)     = __float22bfloat162_rn(make_float2(wv.x, wv.y));
        *(__nv_bfloat162*)(Ws + r * 136 + c4 + 2) = __float22bfloat162_rn(make_float2(wv.z, wv.w));
    }
    __syncthreads();
    int w = tid >> 5, lane = tid & 31;
    int wm = w & 3, wn = w >> 2;
    int g = lane >> 2, tig = lane & 3;
    int mrow = wm * 16, nbase = wn * 32;
    float d[4][4] = {};
    #pragma unroll
    for (int k0 = 0; k0 < 128; k0 += 16) {
        int kc = k0 + 2 * tig;
        unsigned a0 = *(const unsigned*)(As + (mrow + g) * 136 + kc);
        unsigned a1 = *(const unsigned*)(As + (mrow + g + 8) * 136 + kc);
        unsigned a2 = *(const unsigned*)(As + (mrow + g) * 136 + kc + 8);
        unsigned a3 = *(const unsigned*)(As + (mrow + g + 8) * 136 + kc + 8);
        #pragma unroll
        for (int f = 0; f < 4; f++) {
            unsigned b0 = *(const unsigned*)(Ws + (nbase + f * 8 + g) * 136 + kc);
            unsigned b1 = *(const unsigned*)(Ws + (nbase + f * 8 + g) * 136 + kc + 8);
            mma_bf16(d[f], a0, a1, a2, a3, b0, b1);
        }
    }
    #pragma unroll
    for (int f = 0; f < 4; f++) {
        int col = n0 + nbase + f * 8 + 2 * tig;
        float2 b2 = *(const float2*)(bias + col);
        float v00 = d[f][0] + b2.x, v01 = d[f][1] + b2.y;
        float v10 = d[f][2] + b2.x, v11 = d[f][3] + b2.y;
        if (sizeof(OutT) == 4) {
            *(float2*)((float*)C + (m0 + mrow + g) * 384 + col) = make_float2(v00, v01);
            *(float2*)((float*)C + (m0 + mrow + g + 8) * 384 + col) = make_float2(v10, v11);
        } else {
            *(__half2*)((__half*)C + (m0 + mrow + g) * 384 + col) =
                __floats2half2_rn(v00, v01);
            *(__half2*)((__half*)C + (m0 + mrow + g + 8) * 384 + col) =
                __floats2half2_rn(v10, v11);
        }
    }
}

// ---------------- single-step GRU with h0=0 (stage 3) ----------------
__global__ void gru_single(const float* __restrict__ gi, const float* __restrict__ bhh,
                           float* __restrict__ lg)
{
    int idx = blockIdx.x * 256 + threadIdx.x;
    int s = idx >> 7, j = idx & 127;
    const float* gp = gi + (size_t)s * 384;
    float r = sigmoidf_(__ldg(gp + j) + __ldg(bhh + j));
    float z = sigmoidf_(__ldg(gp + 128 + j) + __ldg(bhh + 128 + j));
    float n = tanhf(__ldg(gp + 256 + j) + r * __ldg(bhh + 256 + j));
    lg[idx] = (1.f - z) * n;
}

// ---------------- sector mean: two-phase deterministic strip reduction ----------------
__global__ void __launch_bounds__(128) sector_partial(
    const float* __restrict__ lg, const int* __restrict__ sect,
    float* __restrict__ secp, float* __restrict__ cntp)
{
    int ns = blockIdx.x >> 4, strip = blockIdx.x & 15;
    int d = threadIdx.x;
    float acc = 0.f, c = 0.f;
    #pragma unroll 4
    for (int i = strip * 128; i < strip * 128 + 128; i++) {
        if (__ldg(sect + i) == ns) {
            acc += lg[(size_t)i * 128 + d];
            c += 1.f;
        }
    }
    secp[(size_t)blockIdx.x * 128 + d] = acc;
    if (d == 0) cntp[blockIdx.x] = c;
}
__global__ void __launch_bounds__(128) sector_final(
    const float* __restrict__ secp, const float* __restrict__ cntp,
    float* __restrict__ sec)
{
    int ns = blockIdx.x, d = threadIdx.x;
    float s = 0.f, c = 0.f;
    #pragma unroll
    for (int q = 0; q < 16; q++) {
        s += secp[(size_t)(ns * 16 + q) * 128 + d];
        c += __ldg(cntp + ns * 16 + q);
    }
    sec[ns * 128 + d] = s / fmaxf(c, 1.f);
}

// ---------------- GAT prep ----------------
__global__ void __launch_bounds__(128) gat_prep(
    const float* __restrict__ Hin, int rstride,
    const float* __restrict__ W, const float* __restrict__ a,
    float* __restrict__ Wh, float* __restrict__ s12, int M)
{
    __shared__ float red[4];
    int m = blockIdx.x, n = threadIdx.x;
    const float* hr = Hin + (size_t)m * rstride;
    float acc = 0.f;
    #pragma unroll 8
    for (int k = 0; k < 128; k++) acc = fmaf(__ldg(hr + k), W[k * 128 + n], acc);
    Wh[(size_t)m * 128 + n] = acc;
    float s1 = blockReduceSum128(acc * __ldg(a + n), red);
    float s2 = blockReduceSum128(acc * __ldg(a + 128 + n), red);
    if (n == 0) { s12[m] = s1; s12[M + m] = s2; }
}

// ---------------- GAT intra attention ----------------
__global__ void __launch_bounds__(128) gat_intra_attn(
    const float* __restrict__ Wh, const float* __restrict__ s12,
    const int* __restrict__ sect, float* __restrict__ out)
{
    __shared__ float red[4];
    __shared__ int lst[2048];
    __shared__ float wgt[2048];
    __shared__ int cnt;
    int i = blockIdx.x, d = threadIdx.x;
    if (d == 0) cnt = 0;
    __syncthreads();
    int si = __ldg(sect + i);
    for (int j = d; j < 2048; j += 128)
        if (__ldg(sect + j) == si) { int p = atomicAdd(&cnt, 1); lst[p] = j; }
    __syncthreads();
    int n = cnt;
    float s1i = s12[i];
    float lm = -1e30f;
    for (int p = d; p < n; p += 128) {
        float e = s1i + s12[2048 + lst[p]];
        e = e >= 0.f ? e : 0.2f * e;
        lm = fmaxf(lm, e);
    }
    #pragma unroll
    for (int o = 16; o; o >>= 1) lm = fmaxf(lm, __shfl_xor_sync(0xffffffffu, lm, o));
    if ((d & 31) == 0) red[d >> 5] = lm;
    __syncthreads();
    float m = fmaxf(fmaxf(red[0], red[1]), fmaxf(red[2], red[3]));
    __syncthreads();
    float lz = 0.f;
    for (int p = d; p < n; p += 128) {
        float e = s1i + s12[2048 + lst[p]];
        e = e >= 0.f ? e : 0.2f * e;
        float w = __expf(e - m);
        wgt[p] = w;
        lz += w;
    }
    float Z = blockReduceSum128(lz, red);
    float inv = __fdividef(1.f, Z);
    float acc = 0.f;
    #pragma unroll 4
    for (int p = 0; p < n; p++) acc = fmaf(wgt[p], Wh[(size_t)lst[p] * 128 + d], acc);
    acc *= inv;
    out[(size_t)i * 128 + d] = acc > 0.f ? acc : expm1f(acc);
}

// ---------------- GAT inter attention ----------------
__global__ void __launch_bounds__(128) gat_inter_attn(
    const float* __restrict__ Wh, const float* __restrict__ s12,
    const int* __restrict__ adj, float* __restrict__ out)
{
    __shared__ float e[16];
    int i = blockIdx.x, d = threadIdx.x;
    if (d < 16) {
        float v = s12[i] + s12[16 + d];
        v = v >= 0.f ? v : 0.2f * v;
        e[d] = (__ldg(adj + i * 16 + d) > 0) ? v : -9.0e15f;
    }
    __syncthreads();
    float m = -1e30f;
    #pragma unroll
    for (int j = 0; j < 16; j++) m = fmaxf(m, e[j]);
    float Z = 0.f, acc = 0.f;
    #pragma unroll
    for (int j = 0; j < 16; j++) {
        float w = __expf(e[j] - m);
        Z += w;
        acc = fmaf(w, Wh[j * 128 + d], acc);
    }
    acc = __fdividef(acc, Z);
    out[i * 128 + d] = acc > 0.f ? acc : expm1f(acc);
}

// ---------------- fusion + heads ----------------
__global__ void __launch_bounds__(128) fusion_heads(
    const float* __restrict__ lg, const float* __restrict__ la,
    const float* __restrict__ secout, const int* __restrict__ sect,
    const float* __restrict__ fw, const float* __restrict__ fb,
    const float* __restrict__ rw, const float* __restrict__ rb,
    const float* __restrict__ mw, const float* __restrict__ mb,
    float* __restrict__ out)
{
    __shared__ float red[4];
    int i = blockIdx.x, n = threadIdx.x;
    int si = __ldg(sect + i);
    const float* lgr = lg + (size_t)i * 128;
    const float* lar = la + (size_t)i * 128;
    const float* ser = secout + (size_t)si * 128;
    float acc = __ldg(fb + n);
    #pragma unroll 4
    for (int k = 0; k < 128; k++) acc = fmaf(__ldg(lgr + k), fw[k * 128 + n], acc);
    #pragma unroll 4
    for (int k = 0; k < 128; k++) acc = fmaf(__ldg(lar + k), fw[(128 + k) * 128 + n], acc);
    #pragma unroll 4
    for (int k = 0; k < 128; k++) acc = fmaf(__ldg(ser + k), fw[(256 + k) * 128 + n], acc);
    float r  = blockReduceSum128(acc * __ldg(rw + n), red);
    float mv = blockReduceSum128(acc * __ldg(mw + n), red);
    if (n == 0) {
        out[i]        = r + __ldg(rb);
        out[2048 + i] = sigmoidf_(mv + __ldg(mb));
    }
}

// ---------------- launch ----------------
extern "C" void kernel_launch(void* const* d_in, const int* in_sizes, int n_in,
                              void* d_out, int out_size)
{
    const float* sf    = (const float*)d_in[0];
    const int*   sect  = (const int*)d_in[1];
    const int*   adj   = (const int*)d_in[2];
    const float* g1Wih = (const float*)d_in[3];
    const float* g1Whh = (const float*)d_in[4];
    const float* g1bih = (const float*)d_in[5];
    const float* g1bhh = (const float*)d_in[6];
    const float* a1w   = (const float*)d_in[7];
    const float* a1b   = (const float*)d_in[8];
    const float* giW   = (const float*)d_in[9];
    const float* gia   = (const float*)d_in[10];
    const float* ggWih = (const float*)d_in[11];
    const float* ggWhh = (const float*)d_in[12];
    const float* ggbih = (const float*)d_in[13];
    const float* ggbhh = (const float*)d_in[14];
    const float* agw   = (const float*)d_in[15];
    const float* agb   = (const float*)d_in[16];
    const float* gaWih = (const float*)d_in[17];
    const float* gaWhh = (const float*)d_in[18];
    const float* gabih = (const float*)d_in[19];
    const float* gabhh = (const float*)d_in[20];
    const float* aaw   = (const float*)d_in[21];
    const float* aab   = (const float*)d_in[22];
    const float* geW   = (const float*)d_in[23];
    const float* gea   = (const float*)d_in[24];
    const float* fw    = (const float*)d_in[25];
    const float* fb    = (const float*)d_in[26];
    const float* rw    = (const float*)d_in[27];
    const float* rb    = (const float*)d_in[28];
    const float* mw    = (const float*)d_in[29];
    const float* mb    = (const float*)d_in[30];
    float* out = (float*)d_out;

    float *gif, *gi3, *shortb, *WB1f, *WiBf, *WB4f, *intra, *lgv, *lav, *Wh, *s12,
          *sec, *secp, *cntp, *Wh2, *s12b, *secout;
    cudaGetSymbolAddress((void**)&gif, g_gi);
    cudaGetSymbolAddress((void**)&gi3, g_gi3);
    cudaGetSymbolAddress((void**)&shortb, g_short);
    cudaGetSymbolAddress((void**)&WB1f, g_WB1);
    cudaGetSymbolAddress((void**)&WiBf, g_WiB);
    cudaGetSymbolAddress((void**)&WB4f, g_WB4);
    cudaGetSymbolAddress((void**)&intra, g_intra);
    cudaGetSymbolAddress((void**)&lgv, g_lg);
    cudaGetSymbolAddress((void**)&lav, g_la);
    cudaGetSymbolAddress((void**)&Wh, g_Wh);
    cudaGetSymbolAddress((void**)&s12, g_s12);
    cudaGetSymbolAddress((void**)&sec, g_sec);
    cudaGetSymbolAddress((void**)&secp, g_secp);
    cudaGetSymbolAddress((void**)&cntp, g_cntp);
    cudaGetSymbolAddress((void**)&Wh2, g_Wh2);
    cudaGetSymbolAddress((void**)&s12b, g_s12b);
    cudaGetSymbolAddress((void**)&secout, g_secout);
    __nv_bfloat16* WB1 = (__nv_bfloat16*)WB1f;
    __nv_bfloat16* WiB = (__nv_bfloat16*)WiBf;
    __nv_bfloat16* WB4 = (__nv_bfloat16*)WB4f;
    __half* gih = (__half*)gif;

    static cudaStream_t sB = nullptr;
    static cudaEvent_t evFork = nullptr, evJoin = nullptr;
    if (!sB) {
        cudaStreamCreate(&sB);
        cudaEventCreateWithFlags(&evFork, cudaEventDisableTiming);
        cudaEventCreateWithFlags(&evJoin, cudaEventDisableTiming);
    }

    const int smem1 = 2 * 5 * 16 * 136 * 2 + 2 * 16 * 88 * 2 + 2 * 16 * 5 * 4;  // 49792
    const int smem4 = 32 * 16 * 136 * 2 + 16 * 32 * 4;                           // 141312
    const int smemG = 2 * 64 * 136 * 2;                                          // 34816
    cudaFuncSetAttribute(gru1_dual,
                         cudaFuncAttributeMaxDynamicSharedMemorySize, smem1);
    cudaFuncSetAttribute(gru4,
                         cudaFuncAttributeMaxDynamicSharedMemorySize, smem4);

    conv_all<<<(49152 + 255) / 256, 256>>>(g1Whh, WB1, g1Wih, WiB, gaWhh, WB4);
    gru1_dual<<<148, 512, smem1>>>(
        sf, WiB, WB1, g1bih, g1bhh, a1w, a1b, shortb, 2048);

    // fork: chain B (stage 4, fp16 gi) on stream sB
    cudaEventRecord(evFork, 0);
    cudaStreamWaitEvent(sB, evFork, 0);
    gemm_bf16<__half><<<dim3(65536 / 64, 6), 256, smemG, sB>>>(shortb, gaWih, gabih, gih);
    gru4<<<128, 512, smem4, sB>>>(gih, WB4, gabhh, aaw, aab, lav);
    cudaEventRecord(evJoin, sB);

    // chain A (stream 0)
    gat_prep<<<2048, 128>>>(shortb + 31 * 128, 32 * 128, giW, gia, Wh, s12, 2048);
    gat_intra_attn<<<2048, 128>>>(Wh, s12, sect, intra);
    gemm_bf16<float><<<dim3(2048 / 64, 6), 256, smemG>>>(intra, ggWih, ggbih, gi3);
    gru_single<<<1024, 256>>>(gi3, ggbhh, lgv);
    sector_partial<<<256, 128>>>(lgv, sect, secp, cntp);
    sector_final<<<16, 128>>>(secp, cntp, sec);
    gat_prep<<<16, 128>>>(sec, 128, geW, gea, Wh2, s12b, 16);
    gat_inter_attn<<<16, 128>>>(Wh2, s12b, adj, secout);

    // join
    cudaStreamWaitEvent(0, evJoin, 0);
    fusion_heads<<<2048, 128>>>(lgv, lav, secout, sect, fw, fb, rw, rb, mw, mb, out);
}

// round 15
// speedup vs baseline: 1.7856x; 1.0857x over previous
#include <cuda_runtime.h>
#include <cuda_bf16.h>
#include <cuda_fp16.h>
#include <math.h>

// ---------------- scratch (device globals; no allocation) ----------------
__device__ float g_gi[12582912];    // 65536 x 384 fp16 (as float storage /2)
__device__ float g_gi3[786432];     // 2048 x 384 fp32 (stage 3)
__device__ float g_short[8388608];  // 65536 x 128
__device__ float g_WB1[24576];      // Whh1 bf16 [384][128] (as float storage)
__device__ float g_WiB[3072];       // Wih1 bf16 [384][16]
__device__ float g_WB4[24576];      // gaWhh bf16 [384][128]
__device__ float g_WtG[16384];      // gat_intra_W transposed [n][k] fp32
__device__ float g_WtF[49152];      // fusion_w transposed [n][k] fp32 (k=384)
__device__ float g_intra[262144];
__device__ float g_lg[262144];
__device__ float g_la[262144];
__device__ float g_Wh[262144];      // Wh (chain A), then reused for fused (tail)
__device__ float g_s12[4096];
__device__ float g_sec[2048];
__device__ float g_secp[32768];
__device__ float g_cntp[256];
__device__ float g_Wh2[2048];
__device__ float g_s12b[32];
__device__ float g_secout[2048];

// ---------------- helpers ----------------
__device__ __forceinline__ float sigmoidf_(float x) {
    return __fdividef(1.f, 1.f + __expf(-x));
}
__device__ __forceinline__ float tanhapx_(float x) {
    float y; asm("tanh.approx.f32 %0, %1;" : "=f"(y) : "f"(x)); return y;
}
__device__ __forceinline__ float sigapx_(float x) {
    return fmaf(tanhapx_(0.5f * x), 0.5f, 0.5f);
}
__device__ __forceinline__ unsigned f2tf(float f) {
    unsigned u; asm("cvt.rna.tf32.f32 %0, %1;" : "=r"(u) : "f"(f)); return u;
}
__device__ __forceinline__ void mma_bf16(float d[4], unsigned a0, unsigned a1,
                                         unsigned a2, unsigned a3,
                                         unsigned b0, unsigned b1) {
    asm volatile(
        "mma.sync.aligned.m16n8k16.row.col.f32.bf16.bf16.f32 "
        "{%0,%1,%2,%3},{%4,%5,%6,%7},{%8,%9},{%0,%1,%2,%3};\n"
        : "+f"(d[0]), "+f"(d[1]), "+f"(d[2]), "+f"(d[3])
        : "r"(a0), "r"(a1), "r"(a2), "r"(a3), "r"(b0), "r"(b1));
}
__device__ __forceinline__ void mma_tf32(float d[4], const unsigned a[4],
                                         unsigned b0, unsigned b1) {
    asm volatile(
        "mma.sync.aligned.m16n8k8.row.col.f32.tf32.tf32.f32 "
        "{%0,%1,%2,%3},{%4,%5,%6,%7},{%8,%9},{%0,%1,%2,%3};\n"
        : "+f"(d[0]), "+f"(d[1]), "+f"(d[2]), "+f"(d[3])
        : "r"(a[0]), "r"(a[1]), "r"(a[2]), "r"(a[3]), "r"(b0), "r"(b1));
}
__device__ __forceinline__ float blockReduceSum128(float v, float* red) {
    #pragma unroll
    for (int o = 16; o; o >>= 1) v += __shfl_xor_sync(0xffffffffu, v, o);
    int w = threadIdx.x >> 5;
    if ((threadIdx.x & 31) == 0) red[w] = v;
    __syncthreads();
    float s = red[0] + red[1] + red[2] + red[3];
    __syncthreads();
    return s;
}

// ---------------- fused weight prep: bf16 conversions + fp32 transposes ----------------
__global__ void conv_all(const float* __restrict__ W1, __nv_bfloat16* __restrict__ O1,
                         const float* __restrict__ W2, __nv_bfloat16* __restrict__ O2,
                         const float* __restrict__ W3, __nv_bfloat16* __restrict__ O3,
                         const float* __restrict__ giW, float* __restrict__ WtG,
                         const float* __restrict__ fw, float* __restrict__ WtF) {
    int i = blockIdx.x * 256 + threadIdx.x;
    if (i < 49152) O1[i] = __float2bfloat16(W1[i]);
    if (i < 6144)  O2[i] = __float2bfloat16(W2[i]);
    if (i < 49152) O3[i] = __float2bfloat16(W3[i]);
    if (i < 16384) { int k = i >> 7, n = i & 127; WtG[n * 128 + k] = giW[i]; }
    if (i < 49152) { int k = i / 128, n = i % 128; WtF[n * 384 + k] = fw[i]; }
}

// ---------------- stage-1: dual-batch bf16 GRU + fused pooling, persistent ----------------
__global__ void __launch_bounds__(512, 1) gru1_dual(
    const float* __restrict__ xin,
    const __nv_bfloat16* __restrict__ WiB,
    const __nv_bfloat16* __restrict__ WB,
    const float* __restrict__ bih, const float* __restrict__ bhh,
    const float* __restrict__ aw, const float* __restrict__ ab,
    float* __restrict__ outp, int nPair)
{
    constexpr int T = 5;
    extern __shared__ char smc[];
    __nv_bfloat16* hsm = (__nv_bfloat16*)smc;      // [2][T][16][136]
    __nv_bfloat16* x_b = hsm + 2 * T * 16 * 136;   // [2][16][88]
    float* sc_s = (float*)(x_b + 2 * 16 * 88);     // [2][16][T]

    int tid = threadIdx.x;
    int w = tid >> 5, lane = tid & 31;
    int g = lane >> 2, tig = lane & 3;
    int c0 = w * 8 + 2 * tig;

    unsigned wb[8][3][2];
    #pragma unroll
    for (int kt = 0; kt < 8; kt++) {
        #pragma unroll
        for (int nt = 0; nt < 3; nt++) {
            const __nv_bfloat16* p = WB + (size_t)(nt * 128 + w * 8 + g) * 128 + kt * 16;
            wb[kt][nt][0] = *(const unsigned*)(p + 2 * tig);
            wb[kt][nt][1] = *(const unsigned*)(p + 8 + 2 * tig);
        }
    }
    unsigned wbi[3][2];
    #pragma unroll
    for (int nt = 0; nt < 3; nt++) {
        const __nv_bfloat16* p = WiB + (size_t)(nt * 128 + w * 8 + g) * 16;
        wbi[nt][0] = *(const unsigned*)(p + 2 * tig);
        wbi[nt][1] = *(const unsigned*)(p + 8 + 2 * tig);
    }
    float2 t1, t2;
    t1 = *(const float2*)(bih + c0);       t2 = *(const float2*)(bhh + c0);
    float2 br2 = make_float2(t1.x + t2.x, t1.y + t2.y);
    t1 = *(const float2*)(bih + 128 + c0); t2 = *(const float2*)(bhh + 128 + c0);
    float2 bz2 = make_float2(t1.x + t2.x, t1.y + t2.y);
    float2 bin2 = *(const float2*)(bih + 256 + c0);
    float2 bhn2 = *(const float2*)(bhh + 256 + c0);
    float ab0 = __ldg(ab);
    float awv[4];
    #pragma unroll
    for (int q = 0; q < 4; q++) awv[q] = __ldg(aw + lane + 32 * q);

    float xf[5];
    bool have_pf = false;

    for (int b = blockIdx.x; b < nPair; b += gridDim.x) {
        size_t seq0 = (size_t)b * 32;

        if (!have_pf) {
            for (int i = tid; i < 2560; i += 512) {
                int u = i / 1280, rr = (i % 1280) / 80, col = i % 80;
                x_b[u * (16 * 88) + rr * 88 + col] =
                    __float2bfloat16(__ldg(xin + seq0 * 80 + i));
            }
        } else {
            #pragma unroll
            for (int q = 0; q < 5; q++) {
                int i = tid + q * 512;
                int u = i / 1280, rr = (i % 1280) / 80, col = i % 80;
                x_b[u * (16 * 88) + rr * 88 + col] = __float2bfloat16(xf[q]);
            }
        }
        __syncthreads();

        for (int t = 0; t < T; t++) {
            float aR[2][4] = {}, aZ[2][4] = {}, aN[2][4] = {}, aI[2][4] = {};
            #pragma unroll
            for (int u = 0; u < 2; u++) {
                const __nv_bfloat16* xb = x_b + u * (16 * 88);
                int kc = t * 16 + 2 * tig;
                unsigned a0 = *(const unsigned*)(xb + g * 88 + kc);
                unsigned a1 = *(const unsigned*)(xb + (g + 8) * 88 + kc);
                unsigned a2 = *(const unsigned*)(xb + g * 88 + kc + 8);
                unsigned a3 = *(const unsigned*)(xb + (g + 8) * 88 + kc + 8);
                mma_bf16(aR[u], a0, a1, a2, a3, wbi[0][0], wbi[0][1]);
                mma_bf16(aZ[u], a0, a1, a2, a3, wbi[1][0], wbi[1][1]);
                mma_bf16(aI[u], a0, a1, a2, a3, wbi[2][0], wbi[2][1]);
            }
            if (t > 0) {
                #pragma unroll
                for (int kt = 0; kt < 8; kt++) {
                    #pragma unroll
                    for (int u = 0; u < 2; u++) {
                        const __nv_bfloat16* hb =
                            hsm + u * (T * 16 * 136) + (t - 1) * (16 * 136);
                        int kc = kt * 16 + 2 * tig;
                        unsigned a0 = *(const unsigned*)(hb + g * 136 + kc);
                        unsigned a1 = *(const unsigned*)(hb + (g + 8) * 136 + kc);
                        unsigned a2 = *(const unsigned*)(hb + g * 136 + kc + 8);
                        unsigned a3 = *(const unsigned*)(hb + (g + 8) * 136 + kc + 8);
                        mma_bf16(aR[u], a0, a1, a2, a3, wb[kt][0][0], wb[kt][0][1]);
                        mma_bf16(aZ[u], a0, a1, a2, a3, wb[kt][1][0], wb[kt][1][1]);
                        mma_bf16(aN[u], a0, a1, a2, a3, wb[kt][2][0], wb[kt][2][1]);
                    }
                }
            }
            #pragma unroll
            for (int u = 0; u < 2; u++) {
                __nv_bfloat16* hcur = hsm + u * (T * 16 * 136) + t * (16 * 136);
                const __nv_bfloat16* hprv =
                    hsm + u * (T * 16 * 136) + (t > 0 ? t - 1 : 0) * (16 * 136);
                #pragma unroll
                for (int hh = 0; hh < 2; hh++) {
                    int row = hh ? g + 8 : g;
                    int e = hh * 2;
                    float gr0 = aR[u][e] + br2.x, gr1 = aR[u][e + 1] + br2.y;
                    float gz0 = aZ[u][e] + bz2.x, gz1 = aZ[u][e + 1] + bz2.y;
                    float gn0 = aN[u][e] + bhn2.x, gn1 = aN[u][e + 1] + bhn2.y;
                    float in0 = aI[u][e] + bin2.x, in1 = aI[u][e + 1] + bin2.y;
                    float r0 = sigapx_(gr0), r1 = sigapx_(gr1);
                    float z0 = sigapx_(gz0), z1 = sigapx_(gz1);
                    float n0 = tanhapx_(fmaf(r0, gn0, in0));
                    float n1 = tanhapx_(fmaf(r1, gn1, in1));
                    float h0, h1;
                    if (t == 0) {
                        h0 = (1.f - z0) * n0;
                        h1 = (1.f - z1) * n1;
                    } else {
                        float2 hp2 = __bfloat1622float2(
                            *(const __nv_bfloat162*)(hprv + row * 136 + c0));
                        h0 = fmaf(z0, hp2.x - n0, n0);
                        h1 = fmaf(z1, hp2.y - n1, n1);
                    }
                    *(__nv_bfloat162*)(hcur + row * 136 + c0) =
                        __float22bfloat162_rn(make_float2(h0, h1));
                }
            }
            __syncthreads();
        }

        {
            int bn = b + gridDim.x;
            if (bn < nPair) {
                const float* xp = xin + (size_t)bn * 32 * 80;
                #pragma unroll
                for (int q = 0; q < 5; q++) xf[q] = __ldg(xp + tid + q * 512);
                have_pf = true;
            } else {
                have_pf = false;
            }
        }

        #pragma unroll
        for (int u = 0; u < 2; u++) {
            const __nv_bfloat16* hb = hsm + u * (T * 16 * 136);
            for (int t = 0; t < T; t++) {
                float v = 0.f;
                #pragma unroll
                for (int q = 0; q < 4; q++)
                    v = fmaf(__bfloat162float(hb[t * (16 * 136) + w * 136 + lane + 32 * q]),
                             awv[q], v);
                #pragma unroll
                for (int o = 16; o; o >>= 1) v += __shfl_xor_sync(0xffffffffu, v, o);
                if (lane == 0) sc_s[u * (16 * T) + w * T + t] = v + ab0;
            }
        }
        __syncthreads();
        {
            int j = tid & 127, sb = tid >> 7;
            for (int q = sb; q < 32; q += 4) {
                int u = q >> 4, s = q & 15;
                const __nv_bfloat16* hb = hsm + u * (T * 16 * 136);
                const float* sc = sc_s + u * (16 * T) + s * T;
                float m = -1e30f;
                #pragma unroll
                for (int t = 0; t < T; t++) m = fmaxf(m, sc[t]);
                float Z = 0.f, acc = 0.f;
                #pragma unroll
                for (int t = 0; t < T; t++) {
                    float wt = __expf(sc[t] - m);
                    Z += wt;
                    acc = fmaf(wt, __bfloat162float(hb[t * (16 * 136) + s * 136 + j]), acc);
                }
                outp[(seq0 + u * 16 + s) * 128 + j] = acc / Z;
            }
        }
    }
}

// ---------------- stage-4: bf16 GRU over fp16 gi, fused pooling ----------------
__global__ void __launch_bounds__(512, 1) gru4(
    const __half* __restrict__ gi,
    const __nv_bfloat16* __restrict__ WB,
    const float* __restrict__ bhh,
    const float* __restrict__ aw, const float* __restrict__ ab,
    float* __restrict__ outp)
{
    constexpr int T = 32;
    extern __shared__ char smc[];
    __nv_bfloat16* hsm = (__nv_bfloat16*)smc;
    float* sc_s = (float*)(hsm + T * 16 * 136);

    int tid = threadIdx.x;
    int w = tid >> 5, lane = tid & 31;
    int g = lane >> 2, tig = lane & 3;
    int c0 = w * 8 + 2 * tig;
    size_t seq0 = (size_t)blockIdx.x * 16;

    unsigned wb[8][3][2];
    #pragma unroll
    for (int kt = 0; kt < 8; kt++) {
        #pragma unroll
        for (int nt = 0; nt < 3; nt++) {
            const __nv_bfloat16* p = WB + (size_t)(nt * 128 + w * 8 + g) * 128 + kt * 16;
            wb[kt][nt][0] = *(const unsigned*)(p + 2 * tig);
            wb[kt][nt][1] = *(const unsigned*)(p + 8 + 2 * tig);
        }
    }
    float2 bhr2 = *(const float2*)(bhh + c0);
    float2 bhz2 = *(const float2*)(bhh + 128 + c0);
    float2 bhn2 = *(const float2*)(bhh + 256 + c0);
    float ab0 = __ldg(ab);
    float awv[4];
    #pragma unroll
    for (int q = 0; q < 4; q++) awv[q] = __ldg(aw + lane + 32 * q);
    __syncthreads();

    for (int t = 0; t < T; t++) {
        float ra[4] = {0, 0, 0, 0}, rb[4] = {0, 0, 0, 0};
        float za[4] = {0, 0, 0, 0}, zb[4] = {0, 0, 0, 0};
        float na[4] = {0, 0, 0, 0}, nb[4] = {0, 0, 0, 0};
        float2 pgr[2], pgz[2], pgn[2];
        #pragma unroll
        for (int hh = 0; hh < 2; hh++) {
            int row = hh ? g + 8 : g;
            const __half* gp = gi + ((seq0 + row) * (size_t)T + t) * 384;
            pgr[hh] = __half22float2(*(const __half2*)(gp + c0));
            pgz[hh] = __half22float2(*(const __half2*)(gp + 128 + c0));
            pgn[hh] = __half22float2(*(const __half2*)(gp + 256 + c0));
        }
        if (t > 0) {
            const __nv_bfloat16* hb = hsm + (size_t)(t - 1) * 16 * 136;
            #pragma unroll
            for (int kt = 0; kt < 8; kt++) {
                int kc = kt * 16 + 2 * tig;
                unsigned a0 = *(const unsigned*)(hb + g * 136 + kc);
                unsigned a1 = *(const unsigned*)(hb + (g + 8) * 136 + kc);
                unsigned a2 = *(const unsigned*)(hb + g * 136 + kc + 8);
                unsigned a3 = *(const unsigned*)(hb + (g + 8) * 136 + kc + 8);
                if (kt & 1) {
                    mma_bf16(rb, a0, a1, a2, a3, wb[kt][0][0], wb[kt][0][1]);
                    mma_bf16(zb, a0, a1, a2, a3, wb[kt][1][0], wb[kt][1][1]);
                    mma_bf16(nb, a0, a1, a2, a3, wb[kt][2][0], wb[kt][2][1]);
                } else {
                    mma_bf16(ra, a0, a1, a2, a3, wb[kt][0][0], wb[kt][0][1]);
                    mma_bf16(za, a0, a1, a2, a3, wb[kt][1][0], wb[kt][1][1]);
                    mma_bf16(na, a0, a1, a2, a3, wb[kt][2][0], wb[kt][2][1]);
                }
            }
        }
        {
            __nv_bfloat16* hcur = hsm + (size_t)t * 16 * 136;
            const __nv_bfloat16* hprv = hsm + (size_t)(t > 0 ? t - 1 : 0) * 16 * 136;
            #pragma unroll
            for (int hh = 0; hh < 2; hh++) {
                int row = hh ? g + 8 : g;
                int e = hh * 2;
                float gr0 = ra[e] + rb[e] + bhr2.x + pgr[hh].x;
                float gr1 = ra[e + 1] + rb[e + 1] + bhr2.y + pgr[hh].y;
                float gz0 = za[e] + zb[e] + bhz2.x + pgz[hh].x;
                float gz1 = za[e + 1] + zb[e + 1] + bhz2.y + pgz[hh].y;
                float gn0 = na[e] + nb[e] + bhn2.x;
                float gn1 = na[e + 1] + nb[e + 1] + bhn2.y;
                float r0 = sigapx_(gr0), r1 = sigapx_(gr1);
                float z0 = sigapx_(gz0), z1 = sigapx_(gz1);
                float n0 = tanhapx_(fmaf(r0, gn0, pgn[hh].x));
                float n1 = tanhapx_(fmaf(r1, gn1, pgn[hh].y));
                float h0, h1;
                if (t == 0) {
                    h0 = (1.f - z0) * n0;
                    h1 = (1.f - z1) * n1;
                } else {
                    float2 hp2 = __bfloat1622float2(
                        *(const __nv_bfloat162*)(hprv + row * 136 + c0));
                    h0 = fmaf(z0, hp2.x - n0, n0);
                    h1 = fmaf(z1, hp2.y - n1, n1);
                }
                *(__nv_bfloat162*)(hcur + row * 136 + c0) =
                    __float22bfloat162_rn(make_float2(h0, h1));
            }
        }
        __syncthreads();
    }

    {
        int s = w;
        for (int t = 0; t < T; t++) {
            float v = 0.f;
            #pragma unroll
            for (int q = 0; q < 4; q++)
                v = fmaf(__bfloat162float(hsm[t * 16 * 136 + s * 136 + lane + 32 * q]),
                         awv[q], v);
            #pragma unroll
            for (int o = 16; o; o >>= 1) v += __shfl_xor_sync(0xffffffffu, v, o);
            if (lane == 0) sc_s[s * T + t] = v + ab0;
        }
    }
    __syncthreads();
    {
        int j = tid & 127, sb = tid >> 7;
        #pragma unroll
        for (int i = 0; i < 4; i++) {
            int s = sb + i * 4;
            float m = -1e30f;
            for (int t = 0; t < T; t++) m = fmaxf(m, sc_s[s * T + t]);
            float Z = 0.f, acc = 0.f;
            for (int t = 0; t < T; t++) {
                float wt = __expf(sc_s[s * T + t] - m);
                Z += wt;
                acc = fmaf(wt, __bfloat162float(hsm[t * 16 * 136 + s * 136 + j]), acc);
            }
            outp[(seq0 + s) * 128 + j] = acc / Z;
        }
    }
}

// ---------------- bf16 GEMM: C[M,384] = A[M,128] @ W[384,128]^T + bias ----------------
template<typename OutT>
__global__ void __launch_bounds__(256) gemm_bf16(
    const float* __restrict__ A, const float* __restrict__ W,
    const float* __restrict__ bias, OutT* __restrict__ C)
{
    extern __shared__ char gsc[];
    __nv_bfloat16* As = (__nv_bfloat16*)gsc;
    __nv_bfloat16* Ws = As + 64 * 136;
    int tid = threadIdx.x;
    size_t m0 = (size_t)blockIdx.x * 64;
    int n0 = blockIdx.y * 64;
    for (int i = tid; i < 2048; i += 256) {
        int r = i >> 5, c4 = (i & 31) * 4;
        float4 av = *(const float4*)(A + (m0 + r) * 128 + c4);
        float4 wv = *(const float4*)(W + (size_t)(n0 + r) * 128 + c4);
        *(__nv_bfloat162*)(As + r * 136 + c4)     = __float22bfloat162_rn(make_float2(av.x, av.y));
        *(__nv_bfloat162*)(As + r * 136 + c4 + 2) = __float22bfloat162_rn(make_float2(av.z, av.w));
        *(__nv_bfloat162*)(Ws + r * 136 + c4)     = __float22bfloat162_rn(make_float2(wv.x, wv.y));
        *(__nv_bfloat162*)(Ws + r * 136 + c4 + 2) = __float22bfloat162_rn(make_float2(wv.z, wv.w));
    }
    __syncthreads();
    int w = tid >> 5, lane = tid & 31;
    int wm = w & 3, wn = w >> 2;
    int g = lane >> 2, tig = lane & 3;
    int mrow = wm * 16, nbase = wn * 32;
    float d[4][4] = {};
    #pragma unroll
    for (int k0 = 0; k0 < 128; k0 += 16) {
        int kc = k0 + 2 * tig;
        unsigned a0 = *(const unsigned*)(As + (mrow + g) * 136 + kc);
        unsigned a1 = *(const unsigned*)(As + (mrow + g + 8) * 136 + kc);
        unsigned a2 = *(const unsigned*)(As + (mrow + g) * 136 + kc + 8);
        unsigned a3 = *(const unsigned*)(As + (mrow + g + 8) * 136 + kc + 8);
        #pragma unroll
        for (int f = 0; f < 4; f++) {
            unsigned b0 = *(const unsigned*)(Ws + (nbase + f * 8 + g) * 136 + kc);
            unsigned b1 = *(const unsigned*)(Ws + (nbase + f * 8 + g) * 136 + kc + 8);
            mma_bf16(d[f], a0, a1, a2, a3, b0, b1);
        }
    }
    #pragma unroll
    for (int f = 0; f < 4; f++) {
        int col = n0 + nbase + f * 8 + 2 * tig;
        float2 b2 = *(const float2*)(bias + col);
        float v00 = d[f][0] + b2.x, v01 = d[f][1] + b2.y;
        float v10 = d[f][2] + b2.x, v11 = d[f][3] + b2.y;
        if (sizeof(OutT) == 4) {
            *(float2*)((float*)C + (m0 + mrow + g) * 384 + col) = make_float2(v00, v01);
            *(float2*)((float*)C + (m0 + mrow + g + 8) * 384 + col) = make_float2(v10, v11);
        } else {
            *(__half2*)((__half*)C + (m0 + mrow + g) * 384 + col) =
                __floats2half2_rn(v00, v01);
            *(__half2*)((__half*)C + (m0 + mrow + g + 8) * 384 + col) =
                __floats2half2_rn(v10, v11);
        }
    }
}

// ---------------- tf32 GEMM: Wh[2048][128] = last @ WtG^T (strided A rows) ----------------
__global__ void __launch_bounds__(256) gemm_gat(
    const float* __restrict__ Hin, int rstride,
    const float* __restrict__ Bt,   // [128][128] fp32 (n,k)
    float* __restrict__ C)          // [M][128]
{
    extern __shared__ float gs[];
    float* As = gs;             // 64 x 132
    float* Ws = gs + 64 * 132;  // 64 x 132
    int tid = threadIdx.x;
    size_t m0 = (size_t)blockIdx.x * 64;
    int n0 = blockIdx.y * 64;
    for (int i = tid; i < 2048; i += 256) {
        int r = i >> 5, c4 = (i & 31) * 4;
        float4 av = *(const float4*)(Hin + (m0 + r) * (size_t)rstride + c4);
        float4 wv = *(const float4*)(Bt + (size_t)(n0 + r) * 128 + c4);
        av.x = __uint_as_float(f2tf(av.x)); av.y = __uint_as_float(f2tf(av.y));
        av.z = __uint_as_float(f2tf(av.z)); av.w = __uint_as_float(f2tf(av.w));
        wv.x = __uint_as_float(f2tf(wv.x)); wv.y = __uint_as_float(f2tf(wv.y));
        wv.z = __uint_as_float(f2tf(wv.z)); wv.w = __uint_as_float(f2tf(wv.w));
        *(float4*)(As + r * 132 + c4) = av;
        *(float4*)(Ws + r * 132 + c4) = wv;
    }
    __syncthreads();
    int w = tid >> 5, lane = tid & 31;
    int wm = w & 3, wn = w >> 2;
    int g = lane >> 2, tig = lane & 3;
    int mrow = wm * 16, nbase = wn * 32;
    float d[4][4] = {};
    #pragma unroll
    for (int k0 = 0; k0 < 128; k0 += 8) {
        unsigned a[4];
        a[0] = __float_as_uint(As[(mrow + g) * 132 + k0 + tig]);
        a[1] = __float_as_uint(As[(mrow + g + 8) * 132 + k0 + tig]);
        a[2] = __float_as_uint(As[(mrow + g) * 132 + k0 + tig + 4]);
        a[3] = __float_as_uint(As[(mrow + g + 8) * 132 + k0 + tig + 4]);
        #pragma unroll
        for (int f = 0; f < 4; f++) {
            unsigned b0 = __float_as_uint(Ws[(nbase + f * 8 + g) * 132 + k0 + tig]);
            unsigned b1 = __float_as_uint(Ws[(nbase + f * 8 + g) * 132 + k0 + tig + 4]);
            mma_tf32(d[f], a, b0, b1);
        }
    }
    #pragma unroll
    for (int f = 0; f < 4; f++) {
        int col = n0 + nbase + f * 8 + 2 * tig;
        *(float2*)(C + (m0 + mrow + g) * 128 + col) = make_float2(d[f][0], d[f][1]);
        *(float2*)(C + (m0 + mrow + g + 8) * 128 + col) = make_float2(d[f][2], d[f][3]);
    }
}

// ---------------- tf32 GEMM: fused[2048][128] = concat(lg,la,sec_ps) @ WtF^T + fb ----------------
__global__ void __launch_bounds__(256) gemm_fusion(
    const float* __restrict__ lg, const float* __restrict__ la,
    const float* __restrict__ secout, const int* __restrict__ sect,
    const float* __restrict__ Bt,   // [128][384] fp32 (n,k)
    const float* __restrict__ fb,
    float* __restrict__ C)          // [2048][128]
{
    extern __shared__ float gs[];
    float* As = gs;
    float* Ws = gs + 64 * 132;
    int tid = threadIdx.x;
    size_t m0 = (size_t)blockIdx.x * 64;
    int n0 = blockIdx.y * 64;
    int w = tid >> 5, lane = tid & 31;
    int wm = w & 3, wn = w >> 2;
    int g = lane >> 2, tig = lane & 3;
    int mrow = wm * 16, nbase = wn * 32;
    float d[4][4] = {};
    for (int ch = 0; ch < 3; ch++) {
        for (int i = tid; i < 2048; i += 256) {
            int r = i >> 5, c4 = (i & 31) * 4;
            const float* src;
            if (ch == 0)      src = lg + (m0 + r) * 128;
            else if (ch == 1) src = la + (m0 + r) * 128;
            else              src = secout + (size_t)__ldg(sect + m0 + r) * 128;
            float4 av = *(const float4*)(src + c4);
            float4 wv = *(const float4*)(Bt + (size_t)(n0 + r) * 384 + ch * 128 + c4);
            av.x = __uint_as_float(f2tf(av.x)); av.y = __uint_as_float(f2tf(av.y));
            av.z = __uint_as_float(f2tf(av.z)); av.w = __uint_as_float(f2tf(av.w));
            wv.x = __uint_as_float(f2tf(wv.x)); wv.y = __uint_as_float(f2tf(wv.y));
            wv.z = __uint_as_float(f2tf(wv.z)); wv.w = __uint_as_float(f2tf(wv.w));
            *(float4*)(As + r * 132 + c4) = av;
            *(float4*)(Ws + r * 132 + c4) = wv;
        }
        __syncthreads();
        #pragma unroll
        for (int k0 = 0; k0 < 128; k0 += 8) {
            unsigned a[4];
            a[0] = __float_as_uint(As[(mrow + g) * 132 + k0 + tig]);
            a[1] = __float_as_uint(As[(mrow + g + 8) * 132 + k0 + tig]);
            a[2] = __float_as_uint(As[(mrow + g) * 132 + k0 + tig + 4]);
            a[3] = __float_as_uint(As[(mrow + g + 8) * 132 + k0 + tig + 4]);
            #pragma unroll
            for (int f = 0; f < 4; f++) {
                unsigned b0 = __float_as_uint(Ws[(nbase + f * 8 + g) * 132 + k0 + tig]);
                unsigned b1 = __float_as_uint(Ws[(nbase + f * 8 + g) * 132 + k0 + tig + 4]);
                mma_tf32(d[f], a, b0, b1);
            }
        }
        __syncthreads();
    }
    #pragma unroll
    for (int f = 0; f < 4; f++) {
        int col = n0 + nbase + f * 8 + 2 * tig;
        float2 b2 = *(const float2*)(fb + col);
        *(float2*)(C + (m0 + mrow + g) * 128 + col) =
            make_float2(d[f][0] + b2.x, d[f][1] + b2.y);
        *(float2*)(C + (m0 + mrow + g + 8) * 128 + col) =
            make_float2(d[f][2] + b2.x, d[f][3] + b2.y);
    }
}

// ---------------- s12 from Wh ----------------
__global__ void __launch_bounds__(128) gat_s12(
    const float* __restrict__ Wh, const float* __restrict__ a,
    float* __restrict__ s12, int M)
{
    __shared__ float red[4];
    int m = blockIdx.x, n = threadIdx.x;
    float acc = Wh[(size_t)m * 128 + n];
    float s1 = blockReduceSum128(acc * __ldg(a + n), red);
    float s2 = blockReduceSum128(acc * __ldg(a + 128 + n), red);
    if (n == 0) { s12[m] = s1; s12[M + m] = s2; }
}

// ---------------- heads from fused ----------------
__global__ void __launch_bounds__(128) heads_k(
    const float* __restrict__ fused,
    const float* __restrict__ rw, const float* __restrict__ rb,
    const float* __restrict__ mw, const float* __restrict__ mb,
    float* __restrict__ out)
{
    __shared__ float red[4];
    int i = blockIdx.x, n = threadIdx.x;
    float v = fused[(size_t)i * 128 + n];
    float r  = blockReduceSum128(v * __ldg(rw + n), red);
    float mv = blockReduceSum128(v * __ldg(mw + n), red);
    if (n == 0) {
        out[i]        = r + __ldg(rb);
        out[2048 + i] = sigmoidf_(mv + __ldg(mb));
    }
}

// ---------------- single-step GRU with h0=0 (stage 3) ----------------
__global__ void gru_single(const float* __restrict__ gi, const float* __restrict__ bhh,
                           float* __restrict__ lg)
{
    int idx = blockIdx.x * 256 + threadIdx.x;
    int s = idx >> 7, j = idx & 127;
    const float* gp = gi + (size_t)s * 384;
    float r = sigmoidf_(__ldg(gp + j) + __ldg(bhh + j));
    float z = sigmoidf_(__ldg(gp + 128 + j) + __ldg(bhh + 128 + j));
    float n = tanhf(__ldg(gp + 256 + j) + r * __ldg(bhh + 256 + j));
    lg[idx] = (1.f - z) * n;
}

// ---------------- sector mean: two-phase deterministic strip reduction ----------------
__global__ void __launch_bounds__(128) sector_partial(
    const float* __restrict__ lg, const int* __restrict__ sect,
    float* __restrict__ secp, float* __restrict__ cntp)
{
    int ns = blockIdx.x >> 4, strip = blockIdx.x & 15;
    int d = threadIdx.x;
    float acc = 0.f, c = 0.f;
    #pragma unroll 4
    for (int i = strip * 128; i < strip * 128 + 128; i++) {
        if (__ldg(sect + i) == ns) {
            acc += lg[(size_t)i * 128 + d];
            c += 1.f;
        }
    }
    secp[(size_t)blockIdx.x * 128 + d] = acc;
    if (d == 0) cntp[blockIdx.x] = c;
}
__global__ void __launch_bounds__(128) sector_final(
    const float* __restrict__ secp, const float* __restrict__ cntp,
    float* __restrict__ sec)
{
    int ns = blockIdx.x, d = threadIdx.x;
    float s = 0.f, c = 0.f;
    #pragma unroll
    for (int q = 0; q < 16; q++) {
        s += secp[(size_t)(ns * 16 + q) * 128 + d];
        c += __ldg(cntp + ns * 16 + q);
    }
    sec[ns * 128 + d] = s / fmaxf(c, 1.f);
}

// ---------------- GAT prep (16-row inter case only) ----------------
__global__ void __launch_bounds__(128) gat_prep(
    const float* __restrict__ Hin, int rstride,
    const float* __restrict__ W, const float* __restrict__ a,
    float* __restrict__ Wh, float* __restrict__ s12, int M)
{
    __shared__ float red[4];
    int m = blockIdx.x, n = threadIdx.x;
    const float* hr = Hin + (size_t)m * rstride;
    float acc = 0.f;
    #pragma unroll 8
    for (int k = 0; k < 128; k++) acc = fmaf(__ldg(hr + k), W[k * 128 + n], acc);
    Wh[(size_t)m * 128 + n] = acc;
    float s1 = blockReduceSum128(acc * __ldg(a + n), red);
    float s2 = blockReduceSum128(acc * __ldg(a + 128 + n), red);
    if (n == 0) { s12[m] = s1; s12[M + m] = s2; }
}

// ---------------- GAT intra attention ----------------
__global__ void __launch_bounds__(128) gat_intra_attn(
    const float* __restrict__ Wh, const float* __restrict__ s12,
    const int* __restrict__ sect, float* __restrict__ out)
{
    __shared__ float red[4];
    __shared__ int lst[2048];
    __shared__ float wgt[2048];
    __shared__ int cnt;
    int i = blockIdx.x, d = threadIdx.x;
    if (d == 0) cnt = 0;
    __syncthreads();
    int si = __ldg(sect + i);
    for (int j = d; j < 2048; j += 128)
        if (__ldg(sect + j) == si) { int p = atomicAdd(&cnt, 1); lst[p] = j; }
    __syncthreads();
    int n = cnt;
    float s1i = s12[i];
    float lm = -1e30f;
    for (int p = d; p < n; p += 128) {
        float e = s1i + s12[2048 + lst[p]];
        e = e >= 0.f ? e : 0.2f * e;
        lm = fmaxf(lm, e);
    }
    #pragma unroll
    for (int o = 16; o; o >>= 1) lm = fmaxf(lm, __shfl_xor_sync(0xffffffffu, lm, o));
    if ((d & 31) == 0) red[d >> 5] = lm;
    __syncthreads();
    float m = fmaxf(fmaxf(red[0], red[1]), fmaxf(red[2], red[3]));
    __syncthreads();
    float lz = 0.f;
    for (int p = d; p < n; p += 128) {
        float e = s1i + s12[2048 + lst[p]];
        e = e >= 0.f ? e : 0.2f * e;
        float w = __expf(e - m);
        wgt[p] = w;
        lz += w;
    }
    float Z = blockReduceSum128(lz, red);
    float inv = __fdividef(1.f, Z);
    float acc = 0.f;
    #pragma unroll 4
    for (int p = 0; p < n; p++) acc = fmaf(wgt[p], Wh[(size_t)lst[p] * 128 + d], acc);
    acc *= inv;
    out[(size_t)i * 128 + d] = acc > 0.f ? acc : expm1f(acc);
}

// ---------------- GAT inter attention ----------------
__global__ void __launch_bounds__(128) gat_inter_attn(
    const float* __restrict__ Wh, const float* __restrict__ s12,
    const int* __restrict__ adj, float* __restrict__ out)
{
    __shared__ float e[16];
    int i = blockIdx.x, d = threadIdx.x;
    if (d < 16) {
        float v = s12[i] + s12[16 + d];
        v = v >= 0.f ? v : 0.2f * v;
        e[d] = (__ldg(adj + i * 16 + d) > 0) ? v : -9.0e15f;
    }
    __syncthreads();
    float m = -1e30f;
    #pragma unroll
    for (int j = 0; j < 16; j++) m = fmaxf(m, e[j]);
    float Z = 0.f, acc = 0.f;
    #pragma unroll
    for (int j = 0; j < 16; j++) {
        float w = __expf(e[j] - m);
        Z += w;
        acc = fmaf(w, Wh[j * 128 + d], acc);
    }
    acc = __fdividef(acc, Z);
    out[i * 128 + d] = acc > 0.f ? acc : expm1f(acc);
}

// ---------------- launch ----------------
extern "C" void kernel_launch(void* const* d_in, const int* in_sizes, int n_in,
                              void* d_out, int out_size)
{
    const float* sf    = (const float*)d_in[0];
    const int*   sect  = (const int*)d_in[1];
    const int*   adj   = (const int*)d_in[2];
    const float* g1Wih = (const float*)d_in[3];
    const float* g1Whh = (const float*)d_in[4];
    const float* g1bih = (const float*)d_in[5];
    const float* g1bhh = (const float*)d_in[6];
    const float* a1w   = (const float*)d_in[7];
    const float* a1b   = (const float*)d_in[8];
    const float* giW   = (const float*)d_in[9];
    const float* gia   = (const float*)d_in[10];
    const float* ggWih = (const float*)d_in[11];
    const float* ggWhh = (const float*)d_in[12];
    const float* ggbih = (const float*)d_in[13];
    const float* ggbhh = (const float*)d_in[14];
    const float* agw   = (const float*)d_in[15];
    const float* agb   = (const float*)d_in[16];
    const float* gaWih = (const float*)d_in[17];
    const float* gaWhh = (const float*)d_in[18];
    const float* gabih = (const float*)d_in[19];
    const float* gabhh = (const float*)d_in[20];
    const float* aaw   = (const float*)d_in[21];
    const float* aab   = (const float*)d_in[22];
    const float* geW   = (const float*)d_in[23];
    const float* gea   = (const float*)d_in[24];
    const float* fw    = (const float*)d_in[25];
    const float* fb    = (const float*)d_in[26];
    const float* rw    = (const float*)d_in[27];
    const float* rb    = (const float*)d_in[28];
    const float* mw    = (const float*)d_in[29];
    const float* mb    = (const float*)d_in[30];
    float* out = (float*)d_out;

    float *gif, *gi3, *shortb, *WB1f, *WiBf, *WB4f, *WtG, *WtF, *intra, *lgv, *lav,
          *Wh, *s12, *sec, *secp, *cntp, *Wh2, *s12b, *secout;
    cudaGetSymbolAddress((void**)&gif, g_gi);
    cudaGetSymbolAddress((void**)&gi3, g_gi3);
    cudaGetSymbolAddress((void**)&shortb, g_short);
    cudaGetSymbolAddress((void**)&WB1f, g_WB1);
    cudaGetSymbolAddress((void**)&WiBf, g_WiB);
    cudaGetSymbolAddress((void**)&WB4f, g_WB4);
    cudaGetSymbolAddress((void**)&WtG, g_WtG);
    cudaGetSymbolAddress((void**)&WtF, g_WtF);
    cudaGetSymbolAddress((void**)&intra, g_intra);
    cudaGetSymbolAddress((void**)&lgv, g_lg);
    cudaGetSymbolAddress((void**)&lav, g_la);
    cudaGetSymbolAddress((void**)&Wh, g_Wh);
    cudaGetSymbolAddress((void**)&s12, g_s12);
    cudaGetSymbolAddress((void**)&sec, g_sec);
    cudaGetSymbolAddress((void**)&secp, g_secp);
    cudaGetSymbolAddress((void**)&cntp, g_cntp);
    cudaGetSymbolAddress((void**)&Wh2, g_Wh2);
    cudaGetSymbolAddress((void**)&s12b, g_s12b);
    cudaGetSymbolAddress((void**)&secout, g_secout);
    __nv_bfloat16* WB1 = (__nv_bfloat16*)WB1f;
    __nv_bfloat16* WiB = (__nv_bfloat16*)WiBf;
    __nv_bfloat16* WB4 = (__nv_bfloat16*)WB4f;
    __half* gih = (__half*)gif;

    static cudaStream_t sB = nullptr;
    static cudaEvent_t evFork = nullptr, evJoin = nullptr;
    if (!sB) {
        cudaStreamCreate(&sB);
        cudaEventCreateWithFlags(&evFork, cudaEventDisableTiming);
        cudaEventCreateWithFlags(&evJoin, cudaEventDisableTiming);
    }

    const int smem1 = 2 * 5 * 16 * 136 * 2 + 2 * 16 * 88 * 2 + 2 * 16 * 5 * 4;  // 49792
    const int smem4 = 32 * 16 * 136 * 2 + 16 * 32 * 4;                           // 141312
    const int smemG = 2 * 64 * 136 * 2;                                          // 34816
    const int smemT = 2 * 64 * 132 * 4;                                          // 67584
    cudaFuncSetAttribute(gru1_dual,
                         cudaFuncAttributeMaxDynamicSharedMemorySize, smem1);
    cudaFuncSetAttribute(gru4,
                         cudaFuncAttributeMaxDynamicSharedMemorySize, smem4);
    cudaFuncSetAttribute(gemm_gat,
                         cudaFuncAttributeMaxDynamicSharedMemorySize, smemT);
    cudaFuncSetAttribute(gemm_fusion,
                         cudaFuncAttributeMaxDynamicSharedMemorySize, smemT);

    conv_all<<<(49152 + 255) / 256, 256>>>(g1Whh, WB1, g1Wih, WiB, gaWhh, WB4,
                                           giW, WtG, fw, WtF);
    gru1_dual<<<148, 512, smem1>>>(
        sf, WiB, WB1, g1bih, g1bhh, a1w, a1b, shortb, 2048);

    // fork: chain B (stage 4, fp16 gi) on stream sB
    cudaEventRecord(evFork, 0);
    cudaStreamWaitEvent(sB, evFork, 0);
    gemm_bf16<__half><<<dim3(65536 / 64, 6), 256, smemG, sB>>>(shortb, gaWih, gabih, gih);
    gru4<<<128, 512, smem4, sB>>>(gih, WB4, gabhh, aaw, aab, lav);
    cudaEventRecord(evJoin, sB);

    // chain A (stream 0)
    gemm_gat<<<dim3(32, 2), 256, smemT>>>(shortb + 31 * 128, 32 * 128, WtG, Wh);
    gat_s12<<<2048, 128>>>(Wh, gia, s12, 2048);
    gat_intra_attn<<<2048, 128>>>(Wh, s12, sect, intra);
    gemm_bf16<float><<<dim3(2048 / 64, 6), 256, smemG>>>(intra, ggWih, ggbih, gi3);
    gru_single<<<1024, 256>>>(gi3, ggbhh, lgv);
    sector_partial<<<256, 128>>>(lgv, sect, secp, cntp);
    sector_final<<<16, 128>>>(secp, cntp, sec);
    gat_prep<<<16, 128>>>(sec, 128, geW, gea, Wh2, s12b, 16);
    gat_inter_attn<<<16, 128>>>(Wh2, s12b, adj, secout);

    // join: fusion GEMM + heads (tf32)
    cudaStreamWaitEvent(0, evJoin, 0);
    gemm_fusion<<<dim3(32, 2), 256, smemT>>>(lgv, lav, secout, sect, WtF, fb, Wh);
    heads_k<<<2048, 128>>>(Wh, rw, rb, mw, mb, out);
}